// round 11
// baseline (speedup 1.0000x reference)
#include <cuda_runtime.h>
#include <cuda_bf16.h>
#include <stdint.h>

// ---------------------------------------------------------------------------
// MaxSA R11: persistent dense GEMM (296 CTAs, tile loop) to kill wave
// quantization. Everything else identical to R10 best.
// ---------------------------------------------------------------------------

#define CCH   128
#define HWDIM 224
#define MTOK  50176
#define NPERS 296          // 148 SMs x 2 CTAs

__device__ __align__(16) float g_X  [MTOK * CCH];
__device__ __align__(16) float g_Yn [MTOK * CCH];
__device__ __align__(16) float g_Out[MTOK * CCH];
__device__ __align__(16) __nv_bfloat16 g_Xbf [2u * MTOK * CCH];
__device__ __align__(16) __nv_bfloat16 g_QKVbf[2u * MTOK * 384];
__device__ __align__(16) __nv_bfloat16 g_Obf [2u * MTOK * CCH];
__device__ __align__(16) __nv_bfloat16 g_Ynbf[2u * MTOK * CCH];
__device__ __align__(16) __nv_bfloat16 g_Zbf [2u * MTOK * 512];
__device__ __align__(16) __nv_bfloat16 g_Wbf [786432];

// ------------------------- helpers -----------------------------------------
__device__ __forceinline__ uint32_t smem_u32(const void* p) {
    uint32_t a;
    asm("{ .reg .u64 t; cvta.to.shared.u64 t, %1; cvt.u32.u64 %0, t; }" : "=r"(a) : "l"(p));
    return a;
}
__device__ __forceinline__ void mma_bf16(float* c, const uint32_t* a, const uint32_t* b) {
    asm volatile(
        "mma.sync.aligned.m16n8k16.row.col.f32.bf16.bf16.f32 "
        "{%0,%1,%2,%3}, {%4,%5,%6,%7}, {%8,%9}, {%0,%1,%2,%3};"
        : "+f"(c[0]), "+f"(c[1]), "+f"(c[2]), "+f"(c[3])
        : "r"(a[0]), "r"(a[1]), "r"(a[2]), "r"(a[3]), "r"(b[0]), "r"(b[1]));
}
__device__ __forceinline__ void ldm_x4(uint32_t* r, uint32_t addr) {
    asm volatile("ldmatrix.sync.aligned.m8n8.x4.shared.b16 {%0,%1,%2,%3}, [%4];"
                 : "=r"(r[0]), "=r"(r[1]), "=r"(r[2]), "=r"(r[3]) : "r"(addr));
}
__device__ __forceinline__ void ldm_x4_t(uint32_t* r, uint32_t addr) {
    asm volatile("ldmatrix.sync.aligned.m8n8.x4.trans.shared.b16 {%0,%1,%2,%3}, [%4];"
                 : "=r"(r[0]), "=r"(r[1]), "=r"(r[2]), "=r"(r[3]) : "r"(addr));
}
__device__ __forceinline__ uint32_t pack_hi(float x, float y) {
    return (uint32_t)__bfloat16_as_ushort(__float2bfloat16(x)) |
           ((uint32_t)__bfloat16_as_ushort(__float2bfloat16(y)) << 16);
}
__device__ __forceinline__ uint32_t pack_lo(float x, float y) {
    float xh = __bfloat162float(__float2bfloat16(x));
    float yh = __bfloat162float(__float2bfloat16(y));
    return (uint32_t)__bfloat16_as_ushort(__float2bfloat16(x - xh)) |
           ((uint32_t)__bfloat16_as_ushort(__float2bfloat16(y - yh)) << 16);
}
__device__ __forceinline__ void split_bf(float v, __nv_bfloat16& h, __nv_bfloat16& l) {
    h = __float2bfloat16(v);
    l = __float2bfloat16(v - __bfloat162float(h));
}
__device__ __forceinline__ void cpa16(uint32_t d, const void* s) {
    asm volatile("cp.async.ca.shared.global [%0], [%1], 16;"
                 :: "r"(d), "l"(__cvta_generic_to_global(s)) : "memory");
}
#define CPA_COMMIT asm volatile("cp.async.commit_group;" ::: "memory")
#define CPA_WAIT(n) asm volatile("cp.async.wait_group %0;" :: "n"(n) : "memory")

// ---------------------------------------------------------------------------
// Persistent dense GEMM: 296 CTAs loop over (n,m) tiles. 2-stage cp.async.
// mode 0: fp32 out (+bias,+res). mode 1: bf16 planes (+bias). mode 2: fused LN.
// ---------------------------------------------------------------------------
#define RSA 40
#define RSB 136
#define ASZ (128 * RSA * 2)
#define BSZ (32 * RSB * 2)
#define STG (2 * ASZ + 2 * BSZ)
#define GSMEM (2 * STG)
#define MTILES 392

__global__ void __launch_bounds__(256, 2)
gemm_bf(const __nv_bfloat16* __restrict__ A, long long AMK,
        const __nv_bfloat16* __restrict__ Wt, long long WNK,
        int K, int N,
        const float* __restrict__ bias, const float* __restrict__ res,
        float* __restrict__ C, __nv_bfloat16* __restrict__ Cbf, long long CMK,
        int mode, const float* __restrict__ lng, const float* __restrict__ lnb) {
    extern __shared__ char sm[];
    uint32_t sb = smem_u32(sm);
    int tid = threadIdx.x, wid = tid >> 5, l = tid & 31;
    int wm = (wid & 3) * 32, wn = (wid >> 2) * 64;
    int nc = K >> 5;
    int NT = N >> 7;
    int ntiles = MTILES * NT;

    for (int t = blockIdx.x; t < ntiles; t += gridDim.x) {
        int nt = t / MTILES;
        int mt = t - nt * MTILES;
        long long bm = (long long)mt * 128;
        int bn = nt * 128;

        auto load_tile = [&](int st, int cc) {
            int k0 = cc << 5;
            uint32_t base = sb + st * STG;
#pragma unroll
            for (int i = tid; i < 1024; i += 256) {
                int pl = i >> 9;
                int r = (i >> 2) & 127;
                int c4 = (i & 3) * 8;
                cpa16(base + pl * ASZ + (r * RSA + c4) * 2,
                      A + pl * AMK + (bm + r) * K + k0 + c4);
            }
#pragma unroll
            for (int i = tid; i < 1024; i += 256) {
                int pl = i >> 9;
                int r = (i >> 4) & 31;
                int c8 = (i & 15) * 8;
                cpa16(base + 2 * ASZ + pl * BSZ + (r * RSB + c8) * 2,
                      Wt + pl * WNK + (size_t)(k0 + r) * N + bn + c8);
            }
        };

        float acc[2][8][4];
#pragma unroll
        for (int a = 0; a < 2; a++)
#pragma unroll
            for (int b = 0; b < 8; b++)
#pragma unroll
                for (int c = 0; c < 4; c++) acc[a][b][c] = 0.f;

        load_tile(0, 0);
        CPA_COMMIT;
        for (int c = 0; c < nc; c++) {
            if (c + 1 < nc) {
                load_tile((c + 1) & 1, c + 1);
                CPA_COMMIT;
                CPA_WAIT(1);
            } else {
                CPA_WAIT(0);
            }
            __syncthreads();
            uint32_t base = sb + (c & 1) * STG;

            uint32_t ah[2][2][4], al[2][2][4];
#pragma unroll
            for (int ks = 0; ks < 2; ks++)
#pragma unroll
                for (int mi = 0; mi < 2; mi++) {
                    uint32_t ao = base + ((wm + mi * 16 + (l & 15)) * RSA + ks * 16 + (l >> 4) * 8) * 2;
                    ldm_x4(ah[ks][mi], ao);
                    ldm_x4(al[ks][mi], ao + ASZ);
                }
#pragma unroll
            for (int nf = 0; nf < 8; nf++) {
                uint32_t bo = base + 2 * ASZ +
                              ((((l >> 3) * 8) + (l & 7)) * RSB + wn + nf * 8) * 2;
                uint32_t bh[4], bl[4];
                ldm_x4_t(bh, bo);
                ldm_x4_t(bl, bo + BSZ);
#pragma unroll
                for (int ks = 0; ks < 2; ks++)
#pragma unroll
                    for (int mi = 0; mi < 2; mi++) {
                        mma_bf16(acc[mi][nf], ah[ks][mi], bh + ks * 2);
                        mma_bf16(acc[mi][nf], ah[ks][mi], bl + ks * 2);
                        mma_bf16(acc[mi][nf], al[ks][mi], bh + ks * 2);
                    }
            }
            __syncthreads();
        }

        int r0 = wm + (l >> 2);
        if (mode == 2) {
            float* tile  = (float*)sm;
            float* ps    = (float*)(sm + 66048);
            float* mus   = (float*)(sm + 68096);
            float* rstds = (float*)(sm + 68608);
#pragma unroll
            for (int mi = 0; mi < 2; mi++)
#pragma unroll
                for (int half = 0; half < 2; half++) {
                    int row = r0 + mi * 16 + half * 8;
#pragma unroll
                    for (int nf = 0; nf < 8; nf++) {
                        int col = wn + (l & 3) * 2 + nf * 8;
                        float v0 = acc[mi][nf][half * 2 + 0] + bias[col];
                        float v1 = acc[mi][nf][half * 2 + 1] + bias[col + 1];
                        size_t o = (size_t)(bm + row) * 128 + col;
                        v0 += res[o];
                        v1 += res[o + 1];
                        tile[row * 129 + col] = v0;
                        tile[row * 129 + col + 1] = v1;
                    }
                }
            __syncthreads();
            {
                int row = tid & 127, hf = tid >> 7;
                float s = 0.f, q = 0.f;
#pragma unroll 8
                for (int c2 = 0; c2 < 64; c2++) {
                    float v = tile[row * 129 + hf * 64 + c2];
                    s += v;
                    q += v * v;
                }
                ps[tid] = s;
                ps[256 + tid] = q;
            }
            __syncthreads();
            if (tid < 128) {
                float ss = ps[tid] + ps[tid + 128];
                float qq = ps[256 + tid] + ps[256 + tid + 128];
                float mu = ss * (1.0f / 128.0f);
                float var = qq * (1.0f / 128.0f) - mu * mu;
                mus[tid] = mu;
                rstds[tid] = rsqrtf(var + 1e-5f);
            }
            __syncthreads();
            for (int idx = tid; idx < 16384; idx += 256) {
                int r = idx >> 7, c2 = idx & 127;
                float val = (tile[r * 129 + c2] - mus[r]) * rstds[r] * lng[c2] + lnb[c2];
                size_t o = (size_t)(bm + r) * 128 + c2;
                C[o] = val;
                __nv_bfloat16 h, lo2;
                split_bf(val, h, lo2);
                Cbf[o] = h;
                Cbf[CMK + o] = lo2;
            }
        } else {
            int cb = bn + wn + (l & 3) * 2;
#pragma unroll
            for (int mi = 0; mi < 2; mi++) {
#pragma unroll
                for (int half = 0; half < 2; half++) {
                    long long row = bm + r0 + mi * 16 + half * 8;
#pragma unroll
                    for (int nf = 0; nf < 8; nf++) {
                        int col = cb + nf * 8;
                        float v0 = acc[mi][nf][half * 2 + 0];
                        float v1 = acc[mi][nf][half * 2 + 1];
                        if (bias) { v0 += bias[col]; v1 += bias[col + 1]; }
                        size_t o = (size_t)row * N + col;
                        if (mode == 1) {
                            __nv_bfloat16 h0, l0, h1, l1;
                            split_bf(v0, h0, l0);
                            split_bf(v1, h1, l1);
                            __nv_bfloat162 hh; hh.x = h0; hh.y = h1;
                            __nv_bfloat162 ll; ll.x = l0; ll.y = l1;
                            *(__nv_bfloat162*)(Cbf + o) = hh;
                            *(__nv_bfloat162*)(Cbf + CMK + o) = ll;
                        } else {
                            if (res) { v0 += res[o]; v1 += res[o + 1]; }
                            *(float2*)(C + o) = make_float2(v0, v1);
                        }
                    }
                }
            }
        }
        __syncthreads();   // guard smem reuse by the next tile iteration
    }
}

// ---------------------------------------------------------------------------
// Stage-2 flash attention: 2-stage KV, bf16 bias table, 2 CTAs/SM.
// ---------------------------------------------------------------------------
#define FKV 20480
#define FBIAS 102400
#define FSMEM (102400 + 3969 * 2 + 14)

__global__ void __launch_bounds__(256, 2)
flash2(const __nv_bfloat16* __restrict__ QKVbf, const float* __restrict__ table,
       __nv_bfloat16* __restrict__ Obf) {
    extern __shared__ char fsm[];
    uint32_t sb = smem_u32(fsm);
    __nv_bfloat16* sBias = (__nv_bfloat16*)(fsm + FBIAS);

    int tid = threadIdx.x, wid = tid >> 5, ln = tid & 31;
    int bh = blockIdx.y, b = bh >> 2, h = bh & 3;
    int bq = blockIdx.x * 128;
    const long long QMK = (long long)MTOK * 384;
    const long long OMK = (long long)MTOK * 128;
    long long tok0 = (long long)b * 1024;

    for (int i = tid; i < 3969; i += 256) sBias[i] = __float2bfloat16(table[i * 4 + h]);

#pragma unroll
    for (int i = tid; i < 1024; i += 256) {
        int pl = i >> 9, r = (i >> 2) & 127, c4 = (i & 3) * 8;
        cpa16(sb + pl * 10240 + (r * RSA + c4) * 2,
              QKVbf + pl * QMK + (tok0 + bq + r) * 384 + h * 32 + c4);
    }
    CPA_COMMIT;

    auto load_kv = [&](int kt) {
        uint32_t kbase = sb + FKV + (kt & 1) * 40960;
#pragma unroll
        for (int i = tid; i < 2048; i += 256) {
            int tensor = i >> 10;
            int pl = (i >> 9) & 1;
            int r = (i >> 2) & 127, c4 = (i & 3) * 8;
            cpa16(kbase + tensor * 20480 + pl * 10240 + (r * RSA + c4) * 2,
                  QKVbf + pl * QMK + (tok0 + kt * 128 + r) * 384 + 128 + tensor * 128 + h * 32 + c4);
        }
        CPA_COMMIT;
    };
    load_kv(0);
    CPA_WAIT(1);
    __syncthreads();

    int rbase = wid * 16;
    uint32_t qh[2][4], ql[2][4];
#pragma unroll
    for (int ks = 0; ks < 2; ks++) {
        uint32_t ao = sb + ((rbase + (ln & 15)) * RSA + ks * 16 + (ln >> 4) * 8) * 2;
        ldm_x4(qh[ks], ao);
        ldm_x4(ql[ks], ao + 10240);
    }

    float oacc[4][4];
#pragma unroll
    for (int i = 0; i < 4; i++)
#pragma unroll
        for (int j = 0; j < 4; j++) oacc[i][j] = 0.f;
    float m0 = -1e30f, m1 = -1e30f, ls0 = 0.f, ls1 = 0.f;

    int n0 = bq + rbase + (ln >> 2);
    int n1 = n0 + 8;
    int i1a = n0 >> 5, j1a = n0 & 31;
    int i1b = n1 >> 5, j1b = n1 & 31;
    int mcb = 2 * (ln & 3);
    const float SC = 5.656854249492381f;

    for (int kt = 0; kt < 8; kt++) {
        if (kt + 1 < 8) {
            load_kv(kt + 1);
            CPA_WAIT(1);
        } else {
            CPA_WAIT(0);
        }
        __syncthreads();
        uint32_t kb = sb + FKV + (kt & 1) * 40960;

        float sa[16][4];
#pragma unroll
        for (int nf = 0; nf < 16; nf++) {
            sa[nf][0] = sa[nf][1] = sa[nf][2] = sa[nf][3] = 0.f;
            uint32_t bh4[4], bl4[4];
            uint32_t bo = kb + ((nf * 8 + (ln & 7)) * RSA + (ln >> 3) * 8) * 2;
            ldm_x4(bh4, bo);
            ldm_x4(bl4, bo + 10240);
            mma_bf16(sa[nf], qh[0], bh4 + 0);
            mma_bf16(sa[nf], qh[1], bh4 + 2);
            mma_bf16(sa[nf], qh[0], bl4 + 0);
            mma_bf16(sa[nf], qh[1], bl4 + 2);
            mma_bf16(sa[nf], ql[0], bh4 + 0);
            mma_bf16(sa[nf], ql[1], bh4 + 2);
        }

        float mx0 = -1e30f, mx1 = -1e30f;
#pragma unroll
        for (int nf = 0; nf < 16; nf++) {
            int mc = kt * 128 + nf * 8 + mcb;
            int i2a = mc >> 5, j2a = mc & 31;
            int i2b = (mc + 1) >> 5, j2b = (mc + 1) & 31;
            float s0 = sa[nf][0] * SC + __bfloat162float(sBias[(i1a - i2a + 31) * 63 + (j1a - j2a + 31)]);
            float s1 = sa[nf][1] * SC + __bfloat162float(sBias[(i1a - i2b + 31) * 63 + (j1a - j2b + 31)]);
            float s2 = sa[nf][2] * SC + __bfloat162float(sBias[(i1b - i2a + 31) * 63 + (j1b - j2a + 31)]);
            float s3 = sa[nf][3] * SC + __bfloat162float(sBias[(i1b - i2b + 31) * 63 + (j1b - j2b + 31)]);
            sa[nf][0] = s0; sa[nf][1] = s1; sa[nf][2] = s2; sa[nf][3] = s3;
            mx0 = fmaxf(mx0, fmaxf(s0, s1));
            mx1 = fmaxf(mx1, fmaxf(s2, s3));
        }
        mx0 = fmaxf(mx0, __shfl_xor_sync(0xffffffffu, mx0, 1));
        mx0 = fmaxf(mx0, __shfl_xor_sync(0xffffffffu, mx0, 2));
        mx1 = fmaxf(mx1, __shfl_xor_sync(0xffffffffu, mx1, 1));
        mx1 = fmaxf(mx1, __shfl_xor_sync(0xffffffffu, mx1, 2));
        float mn0 = fmaxf(m0, mx0), mn1 = fmaxf(m1, mx1);
        float f0 = __expf(m0 - mn0), f1 = __expf(m1 - mn1);

        float su0 = 0.f, su1 = 0.f;
#pragma unroll
        for (int nf = 0; nf < 16; nf++) {
            float p0 = __expf(sa[nf][0] - mn0);
            float p1 = __expf(sa[nf][1] - mn0);
            float p2 = __expf(sa[nf][2] - mn1);
            float p3 = __expf(sa[nf][3] - mn1);
            sa[nf][0] = p0; sa[nf][1] = p1; sa[nf][2] = p2; sa[nf][3] = p3;
            su0 += p0 + p1; su1 += p2 + p3;
        }
        su0 += __shfl_xor_sync(0xffffffffu, su0, 1);
        su0 += __shfl_xor_sync(0xffffffffu, su0, 2);
        su1 += __shfl_xor_sync(0xffffffffu, su1, 1);
        su1 += __shfl_xor_sync(0xffffffffu, su1, 2);
        ls0 = ls0 * f0 + su0;
        ls1 = ls1 * f1 + su1;
        m0 = mn0; m1 = mn1;

#pragma unroll
        for (int nd = 0; nd < 4; nd++) {
            oacc[nd][0] *= f0; oacc[nd][1] *= f0;
            oacc[nd][2] *= f1; oacc[nd][3] *= f1;
        }

#pragma unroll
        for (int ks2 = 0; ks2 < 4; ks2++) {
            int k0 = ks2 * 32;
            uint32_t pa0h[4], pa0l[4], pa1h[4], pa1l[4];
            int nfa = 4 * ks2, nfb = nfa + 1, nfc = nfa + 2, nfd = nfa + 3;
            pa0h[0] = pack_hi(sa[nfa][0], sa[nfa][1]);
            pa0h[1] = pack_hi(sa[nfa][2], sa[nfa][3]);
            pa0h[2] = pack_hi(sa[nfb][0], sa[nfb][1]);
            pa0h[3] = pack_hi(sa[nfb][2], sa[nfb][3]);
            pa0l[0] = pack_lo(sa[nfa][0], sa[nfa][1]);
            pa0l[1] = pack_lo(sa[nfa][2], sa[nfa][3]);
            pa0l[2] = pack_lo(sa[nfb][0], sa[nfb][1]);
            pa0l[3] = pack_lo(sa[nfb][2], sa[nfb][3]);
            pa1h[0] = pack_hi(sa[nfc][0], sa[nfc][1]);
            pa1h[1] = pack_hi(sa[nfc][2], sa[nfc][3]);
            pa1h[2] = pack_hi(sa[nfd][0], sa[nfd][1]);
            pa1h[3] = pack_hi(sa[nfd][2], sa[nfd][3]);
            pa1l[0] = pack_lo(sa[nfc][0], sa[nfc][1]);
            pa1l[1] = pack_lo(sa[nfc][2], sa[nfc][3]);
            pa1l[2] = pack_lo(sa[nfd][0], sa[nfd][1]);
            pa1l[3] = pack_lo(sa[nfd][2], sa[nfd][3]);
#pragma unroll
            for (int nd = 0; nd < 4; nd++) {
                uint32_t vh4[4], vl4[4];
                uint32_t vo = kb + 20480 + ((k0 + (ln >> 3) * 8 + (ln & 7)) * RSA + nd * 8) * 2;
                ldm_x4_t(vh4, vo);
                ldm_x4_t(vl4, vo + 10240);
                mma_bf16(oacc[nd], pa0h, vh4 + 0);
                mma_bf16(oacc[nd], pa1h, vh4 + 2);
                mma_bf16(oacc[nd], pa0h, vl4 + 0);
                mma_bf16(oacc[nd], pa1h, vl4 + 2);
                mma_bf16(oacc[nd], pa0l, vh4 + 0);
                mma_bf16(oacc[nd], pa1l, vh4 + 2);
            }
        }
        __syncthreads();
    }

    float inv0 = 1.0f / ls0, inv1 = 1.0f / ls1;
    size_t o0 = (size_t)(tok0 + n0) * 128 + h * 32;
    size_t o1 = (size_t)(tok0 + n1) * 128 + h * 32;
#pragma unroll
    for (int nd = 0; nd < 4; nd++) {
        int d = nd * 8 + mcb;
        float a0 = oacc[nd][0] * inv0, a1 = oacc[nd][1] * inv0;
        float b0 = oacc[nd][2] * inv1, b1 = oacc[nd][3] * inv1;
        __nv_bfloat16 h0, l0, h1, l1;
        split_bf(a0, h0, l0); split_bf(a1, h1, l1);
        __nv_bfloat162 hh; hh.x = h0; hh.y = h1;
        __nv_bfloat162 ll; ll.x = l0; ll.y = l1;
        *(__nv_bfloat162*)(Obf + o0 + d) = hh;
        *(__nv_bfloat162*)(Obf + OMK + o0 + d) = ll;
        split_bf(b0, h0, l0); split_bf(b1, h1, l1);
        hh.x = h0; hh.y = h1; ll.x = l0; ll.y = l1;
        *(__nv_bfloat162*)(Obf + o1 + d) = hh;
        *(__nv_bfloat162*)(Obf + OMK + o1 + d) = ll;
    }
}

// ---------------------------------------------------------------------------
// Stage-1 attention on tensor cores (unchanged).
// ---------------------------------------------------------------------------
#define ASQ 0
#define ASK 10240
#define ASV 20480
#define ASB 30720

__global__ void __launch_bounds__(128)
attn_small_tc(const __nv_bfloat16* __restrict__ QKVbf, const float* __restrict__ table,
              __nv_bfloat16* __restrict__ Obf) {
    __shared__ __align__(16) char sm1[31424];
    uint32_t sb = smem_u32(sm1);
    float* sT = (float*)(sm1 + ASB);

    int tid = threadIdx.x, wid = tid >> 5, ln = tid & 31;
    int bh = blockIdx.x, b = bh >> 2, h = bh & 3;
    const long long QMK = (long long)MTOK * 384;
    const long long OMK = (long long)MTOK * 128;
    long long tokb = (long long)b * 49;

    for (int i = tid; i < 169; i += 128) sT[i] = table[i * 4 + h];
#pragma unroll
    for (int i = tid; i < 1536; i += 128) {
        int tensor = i / 512;
        int pl = (i >> 8) & 1;
        int r = (i >> 2) & 63;
        int c4 = (i & 3) * 8;
        int rc = r < 49 ? r : 48;
        cpa16(sb + tensor * 10240 + pl * 5120 + (r * RSA + c4) * 2,
              QKVbf + pl * QMK + (tokb + rc) * 384 + tensor * 128 + h * 32 + c4);
    }
    CPA_COMMIT;
    CPA_WAIT(0);
    __syncthreads();

    uint32_t qh[2][4], ql[2][4];
#pragma unroll
    for (int ks = 0; ks < 2; ks++) {
        uint32_t ao = sb + ASQ + ((wid * 16 + (ln & 15)) * RSA + ks * 16 + (ln >> 4) * 8) * 2;
        ldm_x4(qh[ks], ao);
        ldm_x4(ql[ks], ao + 5120);
    }

    float sa[8][4];
#pragma unroll
    for (int nf = 0; nf < 8; nf++) {
        sa[nf][0] = sa[nf][1] = sa[nf][2] = sa[nf][3] = 0.f;
        uint32_t bh4[4], bl4[4];
        uint32_t bo = sb + ASK + ((nf * 8 + (ln & 7)) * RSA + (ln >> 3) * 8) * 2;
        ldm_x4(bh4, bo);
        ldm_x4(bl4, bo + 5120);
        mma_bf16(sa[nf], qh[0], bh4 + 0);
        mma_bf16(sa[nf], qh[1], bh4 + 2);
        mma_bf16(sa[nf], qh[0], bl4 + 0);
        mma_bf16(sa[nf], qh[1], bl4 + 2);
        mma_bf16(sa[nf], ql[0], bh4 + 0);
        mma_bf16(sa[nf], ql[1], bh4 + 2);
    }

    int n0 = wid * 16 + (ln >> 2);
    int n1 = n0 + 8;
    int n0c = n0 < 49 ? n0 : 48;
    int n1c = n1 < 49 ? n1 : 48;
    int i1a = n0c / 7, j1a = n0c % 7;
    int i1b = n1c / 7, j1b = n1c % 7;
    int mcb = 2 * (ln & 3);
    const float SC = 5.656854249492381f;

    float mx0 = -1e30f, mx1 = -1e30f;
#pragma unroll
    for (int nf = 0; nf < 8; nf++) {
        int mc = nf * 8 + mcb;
        float s0, s1, s2, s3;
        if (mc < 49) {
            int i2 = mc / 7, j2 = mc % 7;
            s0 = sa[nf][0] * SC + sT[(i1a - i2 + 6) * 13 + (j1a - j2 + 6)];
            s2 = sa[nf][2] * SC + sT[(i1b - i2 + 6) * 13 + (j1b - j2 + 6)];
        } else { s0 = -1e30f; s2 = -1e30f; }
        if (mc + 1 < 49) {
            int i2 = (mc + 1) / 7, j2 = (mc + 1) % 7;
            s1 = sa[nf][1] * SC + sT[(i1a - i2 + 6) * 13 + (j1a - j2 + 6)];
            s3 = sa[nf][3] * SC + sT[(i1b - i2 + 6) * 13 + (j1b - j2 + 6)];
        } else { s1 = -1e30f; s3 = -1e30f; }
        sa[nf][0] = s0; sa[nf][1] = s1; sa[nf][2] = s2; sa[nf][3] = s3;
        mx0 = fmaxf(mx0, fmaxf(s0, s1));
        mx1 = fmaxf(mx1, fmaxf(s2, s3));
    }
    mx0 = fmaxf(mx0, __shfl_xor_sync(0xffffffffu, mx0, 1));
    mx0 = fmaxf(mx0, __shfl_xor_sync(0xffffffffu, mx0, 2));
    mx1 = fmaxf(mx1, __shfl_xor_sync(0xffffffffu, mx1, 1));
    mx1 = fmaxf(mx1, __shfl_xor_sync(0xffffffffu, mx1, 2));

    float ls0 = 0.f, ls1 = 0.f;
#pragma unroll
    for (int nf = 0; nf < 8; nf++) {
        float p0 = __expf(sa[nf][0] - mx0);
        float p1 = __expf(sa[nf][1] - mx0);
        float p2 = __expf(sa[nf][2] - mx1);
        float p3 = __expf(sa[nf][3] - mx1);
        sa[nf][0] = p0; sa[nf][1] = p1; sa[nf][2] = p2; sa[nf][3] = p3;
        ls0 += p0 + p1; ls1 += p2 + p3;
    }
    ls0 += __shfl_xor_sync(0xffffffffu, ls0, 1);
    ls0 += __shfl_xor_sync(0xffffffffu, ls0, 2);
    ls1 += __shfl_xor_sync(0xffffffffu, ls1, 1);
    ls1 += __shfl_xor_sync(0xffffffffu, ls1, 2);

    float oacc[4][4];
#pragma unroll
    for (int i = 0; i < 4; i++)
#pragma unroll
        for (int j = 0; j < 4; j++) oacc[i][j] = 0.f;
#pragma unroll
    for (int ks2 = 0; ks2 < 2; ks2++) {
        int k0 = ks2 * 32;
        uint32_t pa0h[4], pa0l[4], pa1h[4], pa1l[4];
        int nfa = 4 * ks2, nfb = nfa + 1, nfc = nfa + 2, nfd = nfa + 3;
        pa0h[0] = pack_hi(sa[nfa][0], sa[nfa][1]);
        pa0h[1] = pack_hi(sa[nfa][2], sa[nfa][3]);
        pa0h[2] = pack_hi(sa[nfb][0], sa[nfb][1]);
        pa0h[3] = pack_hi(sa[nfb][2], sa[nfb][3]);
        pa0l[0] = pack_lo(sa[nfa][0], sa[nfa][1]);
        pa0l[1] = pack_lo(sa[nfa][2], sa[nfa][3]);
        pa0l[2] = pack_lo(sa[nfb][0], sa[nfb][1]);
        pa0l[3] = pack_lo(sa[nfb][2], sa[nfb][3]);
        pa1h[0] = pack_hi(sa[nfc][0], sa[nfc][1]);
        pa1h[1] = pack_hi(sa[nfc][2], sa[nfc][3]);
        pa1h[2] = pack_hi(sa[nfd][0], sa[nfd][1]);
        pa1h[3] = pack_hi(sa[nfd][2], sa[nfd][3]);
        pa1l[0] = pack_lo(sa[nfc][0], sa[nfc][1]);
        pa1l[1] = pack_lo(sa[nfc][2], sa[nfc][3]);
        pa1l[2] = pack_lo(sa[nfd][0], sa[nfd][1]);
        pa1l[3] = pack_lo(sa[nfd][2], sa[nfd][3]);
#pragma unroll
        for (int nd = 0; nd < 4; nd++) {
            uint32_t vh4[4], vl4[4];
            uint32_t vo = sb + ASV + ((k0 + (ln >> 3) * 8 + (ln & 7)) * RSA + nd * 8) * 2;
            ldm_x4_t(vh4, vo);
            ldm_x4_t(vl4, vo + 5120);
            mma_bf16(oacc[nd], pa0h, vh4 + 0);
            mma_bf16(oacc[nd], pa1h, vh4 + 2);
            mma_bf16(oacc[nd], pa0h, vl4 + 0);
            mma_bf16(oacc[nd], pa1h, vl4 + 2);
            mma_bf16(oacc[nd], pa0l, vh4 + 0);
            mma_bf16(oacc[nd], pa1l, vh4 + 2);
        }
    }

    float inv0 = 1.0f / ls0, inv1 = 1.0f / ls1;
#pragma unroll
    for (int nd = 0; nd < 4; nd++) {
        int d = nd * 8 + mcb;
        if (n0 < 49) {
            size_t o0 = (size_t)(tokb + n0) * 128 + h * 32 + d;
            __nv_bfloat16 h0, l0, h1, l1;
            split_bf(oacc[nd][0] * inv0, h0, l0);
            split_bf(oacc[nd][1] * inv0, h1, l1);
            __nv_bfloat162 hh; hh.x = h0; hh.y = h1;
            __nv_bfloat162 ll; ll.x = l0; ll.y = l1;
            *(__nv_bfloat162*)(Obf + o0) = hh;
            *(__nv_bfloat162*)(Obf + OMK + o0) = ll;
        }
        if (n1 < 49) {
            size_t o1 = (size_t)(tokb + n1) * 128 + h * 32 + d;
            __nv_bfloat16 h0, l0, h1, l1;
            split_bf(oacc[nd][2] * inv1, h0, l0);
            split_bf(oacc[nd][3] * inv1, h1, l1);
            __nv_bfloat162 hh; hh.x = h0; hh.y = h1;
            __nv_bfloat162 ll; ll.x = l0; ll.y = l1;
            *(__nv_bfloat162*)(Obf + o1) = hh;
            *(__nv_bfloat162*)(Obf + OMK + o1) = ll;
        }
    }
}

// ------------------------- permutations ------------------------------------
__global__ void __launch_bounds__(256)
winpart_tile(const float* __restrict__ x, float* __restrict__ X,
             __nv_bfloat16* __restrict__ Xbf) {
    __shared__ float tile[32][65];
    const long long XMK = (long long)MTOK * 128;
    int sp0 = blockIdx.x * 64;
    int c0 = blockIdx.y * 32;
    int tid = threadIdx.x;
    {
        int ci = tid >> 3, si = (tid & 7) * 8;
        const float* p = x + (size_t)(c0 + ci) * MTOK + sp0 + si;
        float4 u0 = *(const float4*)p;
        float4 u1 = *(const float4*)(p + 4);
        tile[ci][si + 0] = u0.x; tile[ci][si + 1] = u0.y;
        tile[ci][si + 2] = u0.z; tile[ci][si + 3] = u0.w;
        tile[ci][si + 4] = u1.x; tile[ci][si + 5] = u1.y;
        tile[ci][si + 6] = u1.z; tile[ci][si + 7] = u1.w;
    }
    __syncthreads();
    {
        int si = tid >> 2, cj = (tid & 3) * 8;
        int sp = sp0 + si;
        int hh = sp / HWDIM, ww = sp % HWDIM;
        int out_t = ((hh / 7) * 32 + (ww / 7)) * 49 + (hh % 7) * 7 + (ww % 7);
        size_t ob = (size_t)out_t * 128 + c0 + cj;
#pragma unroll
        for (int k = 0; k < 8; k++) {
            float v = tile[cj + k][si];
            X[ob + k] = v;
            __nv_bfloat16 h, l;
            split_bf(v, h, l);
            Xbf[ob + k] = h;
            Xbf[XMK + ob + k] = l;
        }
    }
}

__global__ void __launch_bounds__(256)
permute_b2g_tile(const float* __restrict__ A, float* __restrict__ Xg,
                 __nv_bfloat16* __restrict__ Xbf) {
    __shared__ float tile[32][129];
    const long long XMK = (long long)MTOK * 128;
    int ho = blockIdx.x;
    int tok1 = blockIdx.y;
    int hi2 = tok1 / 7, wi2 = tok1 % 7;
    int tid = threadIdx.x;
    for (int i = tid; i < 1024; i += 256) {
        int wo = i >> 5, c4 = (i & 31) * 4;
        float4 u = *(const float4*)(A + ((size_t)((ho * 32 + wo) * 49 + tok1)) * 128 + c4);
        tile[wo][c4 + 0] = u.x; tile[wo][c4 + 1] = u.y;
        tile[wo][c4 + 2] = u.z; tile[wo][c4 + 3] = u.w;
    }
    __syncthreads();
    for (int i = tid; i < 1024; i += 256) {
        int c = i & 127, w4 = (i >> 7) * 4;
        int f = (((c * 32 + ho) * 7 + hi2) * 7 + wi2) * 32;
        int cg = f & 127, s = f >> 7;
        int h2 = s / 224, w2 = s % 224;
        int dtok = ((h2 >> 5) * 7 + (w2 >> 5)) * 1024 + (h2 & 31) * 32 + (w2 & 31);
        size_t d0 = (size_t)dtok * 128 + cg + w4;
        float v0 = tile[w4 + 0][c], v1 = tile[w4 + 1][c];
        float v2 = tile[w4 + 2][c], v3 = tile[w4 + 3][c];
        *(float4*)(Xg + d0) = make_float4(v0, v1, v2, v3);
        uint2 ph, pl2;
        ph.x = pack_hi(v0, v1); ph.y = pack_hi(v2, v3);
        pl2.x = pack_lo(v0, v1); pl2.y = pack_lo(v2, v3);
        *(uint2*)(Xbf + d0) = ph;
        *(uint2*)(Xbf + XMK + d0) = pl2;
    }
}

__global__ void permute_g2out_kernel(const float* __restrict__ A, float* __restrict__ out) {
    int idx = (blockIdx.x * 256 + threadIdx.x) * 4;
    if (idx >= MTOK * CCH) return;
    float4 r;
    float* rp = (float*)&r;
#pragma unroll
    for (int k = 0; k < 4; k++) {
        int id = idx + k;
        int w2 = id % HWDIM;
        int t = id / HWDIM;
        int h2 = t % HWDIM;
        int c2 = t / HWDIM;
        int f = (h2 * HWDIM + w2) * CCH + c2;
        int gwo = f % 7;  f /= 7;
        int gwi = f & 31; f >>= 5;
        int ghi = f & 31; f >>= 5;
        int gho = f % 7;  f /= 7;
        int c = f;
        rp[k] = A[((size_t)((gho * 7 + gwo) * 1024 + ghi * 32 + gwi)) * 128 + c];
    }
    *(float4*)(out + idx) = r;
}

// ------------------------- weight pre-split ---------------------------------
struct WParams {
    const float* src[8];
    __nv_bfloat16* dst[8];
    int N[8];
    int K[8];
};
__global__ void convw8(WParams p) {
    int w = blockIdx.y;
    int N = p.N[w], K = p.K[w];
    int NK = N * K;
    const float* src = p.src[w];
    __nv_bfloat16* dst = p.dst[w];
    for (int idx = blockIdx.x * 256 + threadIdx.x; idx < NK; idx += gridDim.x * 256) {
        int n = idx / K, k = idx % K;
        float v = src[idx];
        __nv_bfloat16 h, l;
        split_bf(v, h, l);
        dst[(size_t)k * N + n] = h;
        dst[(size_t)NK + (size_t)k * N + n] = l;
    }
}

// ------------------------- host orchestration -------------------------------
extern "C" void kernel_launch(void* const* d_in, const int* in_sizes, int n_in,
                              void* d_out, int out_size) {
    const float* x = (const float*)d_in[0];
    const float* bp[10];
    const float* gp[10];
    for (int i = 0; i < 10; i++) bp[i] = (const float*)d_in[1 + i];
    for (int i = 0; i < 10; i++) gp[i] = (const float*)d_in[11 + i];

    cudaFuncSetAttribute(gemm_bf, cudaFuncAttributeMaxDynamicSharedMemorySize, GSMEM);
    cudaFuncSetAttribute(flash2, cudaFuncAttributeMaxDynamicSharedMemorySize, FSMEM);

    float *X, *Yn, *Out;
    __nv_bfloat16 *Xbf, *QKVbf, *Obf, *Ynbf, *Zbf, *Wbf;
    cudaGetSymbolAddress((void**)&X, g_X);
    cudaGetSymbolAddress((void**)&Yn, g_Yn);
    cudaGetSymbolAddress((void**)&Out, g_Out);
    cudaGetSymbolAddress((void**)&Xbf, g_Xbf);
    cudaGetSymbolAddress((void**)&QKVbf, g_QKVbf);
    cudaGetSymbolAddress((void**)&Obf, g_Obf);
    cudaGetSymbolAddress((void**)&Ynbf, g_Ynbf);
    cudaGetSymbolAddress((void**)&Zbf, g_Zbf);
    cudaGetSymbolAddress((void**)&Wbf, g_Wbf);

    const long long XMK = (long long)MTOK * 128;
    const long long QMK = (long long)MTOK * 384;
    const long long ZMK = (long long)MTOK * 512;

    WParams wp;
    wp.src[0] = bp[1]; wp.dst[0] = Wbf + 0;      wp.N[0] = 384; wp.K[0] = 128;
    wp.src[1] = bp[2]; wp.dst[1] = Wbf + 98304;  wp.N[1] = 128; wp.K[1] = 128;
    wp.src[2] = bp[6]; wp.dst[2] = Wbf + 131072; wp.N[2] = 512; wp.K[2] = 128;
    wp.src[3] = bp[8]; wp.dst[3] = Wbf + 262144; wp.N[3] = 128; wp.K[3] = 512;
    wp.src[4] = gp[1]; wp.dst[4] = Wbf + 393216; wp.N[4] = 384; wp.K[4] = 128;
    wp.src[5] = gp[2]; wp.dst[5] = Wbf + 491520; wp.N[5] = 128; wp.K[5] = 128;
    wp.src[6] = gp[6]; wp.dst[6] = Wbf + 524288; wp.N[6] = 512; wp.K[6] = 128;
    wp.src[7] = gp[8]; wp.dst[7] = Wbf + 655360; wp.N[7] = 128; wp.K[7] = 512;
    convw8<<<dim3(64, 8), 256>>>(wp);

    // ================= Stage 1: 7x7 windows ==================
    winpart_tile<<<dim3(MTOK / 64, 4), 256>>>(x, X, Xbf);
    gemm_bf<<<NPERS, 256, GSMEM>>>(Xbf, XMK, Wbf + 0, 49152, 128, 384,
                                   nullptr, nullptr, nullptr, QKVbf, QMK, 1, nullptr, nullptr);
    attn_small_tc<<<4096, 128>>>(QKVbf, bp[0], Obf);
    gemm_bf<<<NPERS, 256, GSMEM>>>(Obf, XMK, Wbf + 98304, 16384, 128, 128,
                                   bp[3], X, Yn, Ynbf, XMK, 2, bp[4], bp[5]);
    gemm_bf<<<NPERS, 256, GSMEM>>>(Ynbf, XMK, Wbf + 131072, 65536, 128, 512,
                                   bp[7], nullptr, nullptr, Zbf, ZMK, 1, nullptr, nullptr);
    gemm_bf<<<NPERS, 256, GSMEM>>>(Zbf, ZMK, Wbf + 262144, 65536, 512, 128,
                                   bp[9], Yn, Out, nullptr, 0, 0, nullptr, nullptr);

    permute_b2g_tile<<<dim3(32, 49), 256>>>(Out, X, Xbf);

    // ================= Stage 2: 32x32 grid ===================
    gemm_bf<<<NPERS, 256, GSMEM>>>(Xbf, XMK, Wbf + 393216, 49152, 128, 384,
                                   nullptr, nullptr, nullptr, QKVbf, QMK, 1, nullptr, nullptr);
    flash2<<<dim3(8, 196), 256, FSMEM>>>(QKVbf, gp[0], Obf);
    gemm_bf<<<NPERS, 256, GSMEM>>>(Obf, XMK, Wbf + 491520, 16384, 128, 128,
                                   gp[3], X, Yn, Ynbf, XMK, 2, gp[4], gp[5]);
    gemm_bf<<<NPERS, 256, GSMEM>>>(Ynbf, XMK, Wbf + 524288, 65536, 128, 512,
                                   gp[7], nullptr, nullptr, Zbf, ZMK, 1, nullptr, nullptr);
    gemm_bf<<<NPERS, 256, GSMEM>>>(Zbf, ZMK, Wbf + 655360, 65536, 512, 128,
                                   gp[9], Yn, Out, nullptr, 0, 0, nullptr, nullptr);

    permute_g2out_kernel<<<MTOK * CCH / 1024, 256>>>(Out, (float*)d_out);
}

// round 12
// speedup vs baseline: 1.0487x; 1.0487x over previous
#include <cuda_runtime.h>
#include <cuda_bf16.h>
#include <stdint.h>

// ---------------------------------------------------------------------------
// MaxSA R12: fp32 shadow tensors removed. Activations live as bf16 hi/lo
// planes only; residuals/LN reconstruct (hi+lo). Stage-2 fc2 keeps fp32 out
// for the scattered final permute. flash2/attn/gemm cores as in R10 best.
// ---------------------------------------------------------------------------

#define CCH   128
#define HWDIM 224
#define MTOK  50176

__device__ __align__(16) float g_Out[MTOK * CCH];                 // stage2 fc2 -> g2out
__device__ __align__(16) __nv_bfloat16 g_Xbf [2u * MTOK * CCH];
__device__ __align__(16) __nv_bfloat16 g_QKVbf[2u * MTOK * 384];
__device__ __align__(16) __nv_bfloat16 g_Obf [2u * MTOK * CCH];   // attn out; reused for stage1 fc2 out
__device__ __align__(16) __nv_bfloat16 g_Ynbf[2u * MTOK * CCH];
__device__ __align__(16) __nv_bfloat16 g_Zbf [2u * MTOK * 512];
__device__ __align__(16) __nv_bfloat16 g_Wbf [786432];

// ------------------------- helpers -----------------------------------------
__device__ __forceinline__ uint32_t smem_u32(const void* p) {
    uint32_t a;
    asm("{ .reg .u64 t; cvta.to.shared.u64 t, %1; cvt.u32.u64 %0, t; }" : "=r"(a) : "l"(p));
    return a;
}
__device__ __forceinline__ void mma_bf16(float* c, const uint32_t* a, const uint32_t* b) {
    asm volatile(
        "mma.sync.aligned.m16n8k16.row.col.f32.bf16.bf16.f32 "
        "{%0,%1,%2,%3}, {%4,%5,%6,%7}, {%8,%9}, {%0,%1,%2,%3};"
        : "+f"(c[0]), "+f"(c[1]), "+f"(c[2]), "+f"(c[3])
        : "r"(a[0]), "r"(a[1]), "r"(a[2]), "r"(a[3]), "r"(b[0]), "r"(b[1]));
}
__device__ __forceinline__ void ldm_x4(uint32_t* r, uint32_t addr) {
    asm volatile("ldmatrix.sync.aligned.m8n8.x4.shared.b16 {%0,%1,%2,%3}, [%4];"
                 : "=r"(r[0]), "=r"(r[1]), "=r"(r[2]), "=r"(r[3]) : "r"(addr));
}
__device__ __forceinline__ void ldm_x4_t(uint32_t* r, uint32_t addr) {
    asm volatile("ldmatrix.sync.aligned.m8n8.x4.trans.shared.b16 {%0,%1,%2,%3}, [%4];"
                 : "=r"(r[0]), "=r"(r[1]), "=r"(r[2]), "=r"(r[3]) : "r"(addr));
}
__device__ __forceinline__ uint32_t pack_hi(float x, float y) {
    return (uint32_t)__bfloat16_as_ushort(__float2bfloat16(x)) |
           ((uint32_t)__bfloat16_as_ushort(__float2bfloat16(y)) << 16);
}
__device__ __forceinline__ uint32_t pack_lo(float x, float y) {
    float xh = __bfloat162float(__float2bfloat16(x));
    float yh = __bfloat162float(__float2bfloat16(y));
    return (uint32_t)__bfloat16_as_ushort(__float2bfloat16(x - xh)) |
           ((uint32_t)__bfloat16_as_ushort(__float2bfloat16(y - yh)) << 16);
}
__device__ __forceinline__ void split_bf(float v, __nv_bfloat16& h, __nv_bfloat16& l) {
    h = __float2bfloat16(v);
    l = __float2bfloat16(v - __bfloat162float(h));
}
// reconstruct two consecutive fp32 values from hi/lo planes at element offset o
__device__ __forceinline__ float2 rec2(const __nv_bfloat16* p, long long RMK, size_t o) {
    __nv_bfloat162 h = *(const __nv_bfloat162*)(p + o);
    __nv_bfloat162 l = *(const __nv_bfloat162*)(p + RMK + o);
    return make_float2(__bfloat162float(h.x) + __bfloat162float(l.x),
                       __bfloat162float(h.y) + __bfloat162float(l.y));
}
__device__ __forceinline__ void cpa16(uint32_t d, const void* s) {
    asm volatile("cp.async.ca.shared.global [%0], [%1], 16;"
                 :: "r"(d), "l"(__cvta_generic_to_global(s)) : "memory");
}
#define CPA_COMMIT asm volatile("cp.async.commit_group;" ::: "memory")
#define CPA_WAIT(n) asm volatile("cp.async.wait_group %0;" :: "n"(n) : "memory")

// ---------------------------------------------------------------------------
// Dense GEMM: 2-stage cp.async, 75.8 KB smem, 2 CTAs/SM.
// mode 0: fp32 out (+bias, +res-from-planes)      [stage2 fc2]
// mode 1: bf16-plane out (+bias)                  [qkv, fc1]
// mode 3: bf16-plane out (+bias, +res-from-planes)[stage1 fc2]
// mode 2: fused LN (+bias, +res-from-planes), plane out [proj]
// ---------------------------------------------------------------------------
#define RSA 40
#define RSB 136
#define ASZ (128 * RSA * 2)
#define BSZ (32 * RSB * 2)
#define STG (2 * ASZ + 2 * BSZ)
#define GSMEM (2 * STG)

__global__ void __launch_bounds__(256, 2)
gemm_bf(const __nv_bfloat16* __restrict__ A, long long AMK,
        const __nv_bfloat16* __restrict__ Wt, long long WNK,
        int K, int N,
        const float* __restrict__ bias,
        const __nv_bfloat16* __restrict__ resbf, long long RMK,
        float* __restrict__ C, __nv_bfloat16* __restrict__ Cbf, long long CMK,
        int mode, const float* __restrict__ lng, const float* __restrict__ lnb) {
    extern __shared__ char sm[];
    uint32_t sb = smem_u32(sm);
    int tid = threadIdx.x, wid = tid >> 5, l = tid & 31;
    long long bm = (long long)blockIdx.x * 128;
    int bn = blockIdx.y * 128;
    int wm = (wid & 3) * 32, wn = (wid >> 2) * 64;
    int nc = K >> 5;

    auto load_tile = [&](int st, int cc) {
        int k0 = cc << 5;
        uint32_t base = sb + st * STG;
#pragma unroll
        for (int i = tid; i < 1024; i += 256) {
            int pl = i >> 9;
            int r = (i >> 2) & 127;
            int c4 = (i & 3) * 8;
            cpa16(base + pl * ASZ + (r * RSA + c4) * 2,
                  A + pl * AMK + (bm + r) * K + k0 + c4);
        }
#pragma unroll
        for (int i = tid; i < 1024; i += 256) {
            int pl = i >> 9;
            int r = (i >> 4) & 31;
            int c8 = (i & 15) * 8;
            cpa16(base + 2 * ASZ + pl * BSZ + (r * RSB + c8) * 2,
                  Wt + pl * WNK + (size_t)(k0 + r) * N + bn + c8);
        }
    };

    float acc[2][8][4];
#pragma unroll
    for (int a = 0; a < 2; a++)
#pragma unroll
        for (int b = 0; b < 8; b++)
#pragma unroll
            for (int c = 0; c < 4; c++) acc[a][b][c] = 0.f;

    load_tile(0, 0);
    CPA_COMMIT;
    for (int c = 0; c < nc; c++) {
        if (c + 1 < nc) {
            load_tile((c + 1) & 1, c + 1);
            CPA_COMMIT;
            CPA_WAIT(1);
        } else {
            CPA_WAIT(0);
        }
        __syncthreads();
        uint32_t base = sb + (c & 1) * STG;

        uint32_t ah[2][2][4], al[2][2][4];
#pragma unroll
        for (int ks = 0; ks < 2; ks++)
#pragma unroll
            for (int mi = 0; mi < 2; mi++) {
                uint32_t ao = base + ((wm + mi * 16 + (l & 15)) * RSA + ks * 16 + (l >> 4) * 8) * 2;
                ldm_x4(ah[ks][mi], ao);
                ldm_x4(al[ks][mi], ao + ASZ);
            }
#pragma unroll
        for (int nf = 0; nf < 8; nf++) {
            uint32_t bo = base + 2 * ASZ +
                          ((((l >> 3) * 8) + (l & 7)) * RSB + wn + nf * 8) * 2;
            uint32_t bh[4], bl[4];
            ldm_x4_t(bh, bo);
            ldm_x4_t(bl, bo + BSZ);
#pragma unroll
            for (int ks = 0; ks < 2; ks++)
#pragma unroll
                for (int mi = 0; mi < 2; mi++) {
                    mma_bf16(acc[mi][nf], ah[ks][mi], bh + ks * 2);
                    mma_bf16(acc[mi][nf], ah[ks][mi], bl + ks * 2);
                    mma_bf16(acc[mi][nf], al[ks][mi], bh + ks * 2);
                }
        }
        __syncthreads();
    }

    int r0 = wm + (l >> 2);
    if (mode == 2) {
        // ---- fused LayerNorm epilogue (N == 128, bn == 0); plane output ----
        float* tile  = (float*)sm;
        float* ps    = (float*)(sm + 66048);
        float* mus   = (float*)(sm + 68096);
        float* rstds = (float*)(sm + 68608);
#pragma unroll
        for (int mi = 0; mi < 2; mi++)
#pragma unroll
            for (int half = 0; half < 2; half++) {
                int row = r0 + mi * 16 + half * 8;
#pragma unroll
                for (int nf = 0; nf < 8; nf++) {
                    int col = wn + (l & 3) * 2 + nf * 8;
                    size_t o = (size_t)(bm + row) * 128 + col;
                    float2 rr = rec2(resbf, RMK, o);
                    tile[row * 129 + col]     = acc[mi][nf][half * 2 + 0] + bias[col] + rr.x;
                    tile[row * 129 + col + 1] = acc[mi][nf][half * 2 + 1] + bias[col + 1] + rr.y;
                }
            }
        __syncthreads();
        {
            int row = tid & 127, hf = tid >> 7;
            float s = 0.f, q = 0.f;
#pragma unroll 8
            for (int c2 = 0; c2 < 64; c2++) {
                float v = tile[row * 129 + hf * 64 + c2];
                s += v;
                q += v * v;
            }
            ps[tid] = s;
            ps[256 + tid] = q;
        }
        __syncthreads();
        if (tid < 128) {
            float ss = ps[tid] + ps[tid + 128];
            float qq = ps[256 + tid] + ps[256 + tid + 128];
            float mu = ss * (1.0f / 128.0f);
            float var = qq * (1.0f / 128.0f) - mu * mu;
            mus[tid] = mu;
            rstds[tid] = rsqrtf(var + 1e-5f);
        }
        __syncthreads();
        for (int idx = tid; idx < 16384; idx += 256) {
            int r = idx >> 7, c2 = idx & 127;
            float val = (tile[r * 129 + c2] - mus[r]) * rstds[r] * lng[c2] + lnb[c2];
            size_t o = (size_t)(bm + r) * 128 + c2;
            __nv_bfloat16 h, lo2;
            split_bf(val, h, lo2);
            Cbf[o] = h;
            Cbf[CMK + o] = lo2;
        }
        return;
    }

    int cb = bn + wn + (l & 3) * 2;
#pragma unroll
    for (int mi = 0; mi < 2; mi++) {
#pragma unroll
        for (int half = 0; half < 2; half++) {
            long long row = bm + r0 + mi * 16 + half * 8;
#pragma unroll
            for (int nf = 0; nf < 8; nf++) {
                int col = cb + nf * 8;
                float v0 = acc[mi][nf][half * 2 + 0];
                float v1 = acc[mi][nf][half * 2 + 1];
                if (bias) { v0 += bias[col]; v1 += bias[col + 1]; }
                size_t o = (size_t)row * N + col;
                if (mode != 1 && resbf) {
                    float2 rr = rec2(resbf, RMK, o);
                    v0 += rr.x;
                    v1 += rr.y;
                }
                if (mode == 0) {
                    *(float2*)(C + o) = make_float2(v0, v1);
                } else {
                    __nv_bfloat16 h0, l0, h1, l1;
                    split_bf(v0, h0, l0);
                    split_bf(v1, h1, l1);
                    __nv_bfloat162 hh; hh.x = h0; hh.y = h1;
                    __nv_bfloat162 ll; ll.x = l0; ll.y = l1;
                    *(__nv_bfloat162*)(Cbf + o) = hh;
                    *(__nv_bfloat162*)(Cbf + CMK + o) = ll;
                }
            }
        }
    }
}

// ---------------------------------------------------------------------------
// Stage-2 flash attention: 2-stage KV, bf16 bias table, 2 CTAs/SM (R10).
// ---------------------------------------------------------------------------
#define FKV 20480
#define FBIAS 102400
#define FSMEM (102400 + 3969 * 2 + 14)

__global__ void __launch_bounds__(256, 2)
flash2(const __nv_bfloat16* __restrict__ QKVbf, const float* __restrict__ table,
       __nv_bfloat16* __restrict__ Obf) {
    extern __shared__ char fsm[];
    uint32_t sb = smem_u32(fsm);
    __nv_bfloat16* sBias = (__nv_bfloat16*)(fsm + FBIAS);

    int tid = threadIdx.x, wid = tid >> 5, ln = tid & 31;
    int bh = blockIdx.y, b = bh >> 2, h = bh & 3;
    int bq = blockIdx.x * 128;
    const long long QMK = (long long)MTOK * 384;
    const long long OMK = (long long)MTOK * 128;
    long long tok0 = (long long)b * 1024;

    for (int i = tid; i < 3969; i += 256) sBias[i] = __float2bfloat16(table[i * 4 + h]);

#pragma unroll
    for (int i = tid; i < 1024; i += 256) {
        int pl = i >> 9, r = (i >> 2) & 127, c4 = (i & 3) * 8;
        cpa16(sb + pl * 10240 + (r * RSA + c4) * 2,
              QKVbf + pl * QMK + (tok0 + bq + r) * 384 + h * 32 + c4);
    }
    CPA_COMMIT;

    auto load_kv = [&](int kt) {
        uint32_t kbase = sb + FKV + (kt & 1) * 40960;
#pragma unroll
        for (int i = tid; i < 2048; i += 256) {
            int tensor = i >> 10;
            int pl = (i >> 9) & 1;
            int r = (i >> 2) & 127, c4 = (i & 3) * 8;
            cpa16(kbase + tensor * 20480 + pl * 10240 + (r * RSA + c4) * 2,
                  QKVbf + pl * QMK + (tok0 + kt * 128 + r) * 384 + 128 + tensor * 128 + h * 32 + c4);
        }
        CPA_COMMIT;
    };
    load_kv(0);
    CPA_WAIT(1);
    __syncthreads();

    int rbase = wid * 16;
    uint32_t qh[2][4], ql[2][4];
#pragma unroll
    for (int ks = 0; ks < 2; ks++) {
        uint32_t ao = sb + ((rbase + (ln & 15)) * RSA + ks * 16 + (ln >> 4) * 8) * 2;
        ldm_x4(qh[ks], ao);
        ldm_x4(ql[ks], ao + 10240);
    }

    float oacc[4][4];
#pragma unroll
    for (int i = 0; i < 4; i++)
#pragma unroll
        for (int j = 0; j < 4; j++) oacc[i][j] = 0.f;
    float m0 = -1e30f, m1 = -1e30f, ls0 = 0.f, ls1 = 0.f;

    int n0 = bq + rbase + (ln >> 2);
    int n1 = n0 + 8;
    int i1a = n0 >> 5, j1a = n0 & 31;
    int i1b = n1 >> 5, j1b = n1 & 31;
    int mcb = 2 * (ln & 3);
    const float SC = 5.656854249492381f;

    for (int kt = 0; kt < 8; kt++) {
        if (kt + 1 < 8) {
            load_kv(kt + 1);
            CPA_WAIT(1);
        } else {
            CPA_WAIT(0);
        }
        __syncthreads();
        uint32_t kb = sb + FKV + (kt & 1) * 40960;

        float sa[16][4];
#pragma unroll
        for (int nf = 0; nf < 16; nf++) {
            sa[nf][0] = sa[nf][1] = sa[nf][2] = sa[nf][3] = 0.f;
            uint32_t bh4[4], bl4[4];
            uint32_t bo = kb + ((nf * 8 + (ln & 7)) * RSA + (ln >> 3) * 8) * 2;
            ldm_x4(bh4, bo);
            ldm_x4(bl4, bo + 10240);
            mma_bf16(sa[nf], qh[0], bh4 + 0);
            mma_bf16(sa[nf], qh[1], bh4 + 2);
            mma_bf16(sa[nf], qh[0], bl4 + 0);
            mma_bf16(sa[nf], qh[1], bl4 + 2);
            mma_bf16(sa[nf], ql[0], bh4 + 0);
            mma_bf16(sa[nf], ql[1], bh4 + 2);
        }

        float mx0 = -1e30f, mx1 = -1e30f;
#pragma unroll
        for (int nf = 0; nf < 16; nf++) {
            int mc = kt * 128 + nf * 8 + mcb;
            int i2a = mc >> 5, j2a = mc & 31;
            int i2b = (mc + 1) >> 5, j2b = (mc + 1) & 31;
            float s0 = sa[nf][0] * SC + __bfloat162float(sBias[(i1a - i2a + 31) * 63 + (j1a - j2a + 31)]);
            float s1 = sa[nf][1] * SC + __bfloat162float(sBias[(i1a - i2b + 31) * 63 + (j1a - j2b + 31)]);
            float s2 = sa[nf][2] * SC + __bfloat162float(sBias[(i1b - i2a + 31) * 63 + (j1b - j2a + 31)]);
            float s3 = sa[nf][3] * SC + __bfloat162float(sBias[(i1b - i2b + 31) * 63 + (j1b - j2b + 31)]);
            sa[nf][0] = s0; sa[nf][1] = s1; sa[nf][2] = s2; sa[nf][3] = s3;
            mx0 = fmaxf(mx0, fmaxf(s0, s1));
            mx1 = fmaxf(mx1, fmaxf(s2, s3));
        }
        mx0 = fmaxf(mx0, __shfl_xor_sync(0xffffffffu, mx0, 1));
        mx0 = fmaxf(mx0, __shfl_xor_sync(0xffffffffu, mx0, 2));
        mx1 = fmaxf(mx1, __shfl_xor_sync(0xffffffffu, mx1, 1));
        mx1 = fmaxf(mx1, __shfl_xor_sync(0xffffffffu, mx1, 2));
        float mn0 = fmaxf(m0, mx0), mn1 = fmaxf(m1, mx1);
        float f0 = __expf(m0 - mn0), f1 = __expf(m1 - mn1);

        float su0 = 0.f, su1 = 0.f;
#pragma unroll
        for (int nf = 0; nf < 16; nf++) {
            float p0 = __expf(sa[nf][0] - mn0);
            float p1 = __expf(sa[nf][1] - mn0);
            float p2 = __expf(sa[nf][2] - mn1);
            float p3 = __expf(sa[nf][3] - mn1);
            sa[nf][0] = p0; sa[nf][1] = p1; sa[nf][2] = p2; sa[nf][3] = p3;
            su0 += p0 + p1; su1 += p2 + p3;
        }
        su0 += __shfl_xor_sync(0xffffffffu, su0, 1);
        su0 += __shfl_xor_sync(0xffffffffu, su0, 2);
        su1 += __shfl_xor_sync(0xffffffffu, su1, 1);
        su1 += __shfl_xor_sync(0xffffffffu, su1, 2);
        ls0 = ls0 * f0 + su0;
        ls1 = ls1 * f1 + su1;
        m0 = mn0; m1 = mn1;

#pragma unroll
        for (int nd = 0; nd < 4; nd++) {
            oacc[nd][0] *= f0; oacc[nd][1] *= f0;
            oacc[nd][2] *= f1; oacc[nd][3] *= f1;
        }

#pragma unroll
        for (int ks2 = 0; ks2 < 4; ks2++) {
            int k0 = ks2 * 32;
            uint32_t pa0h[4], pa0l[4], pa1h[4], pa1l[4];
            int nfa = 4 * ks2, nfb = nfa + 1, nfc = nfa + 2, nfd = nfa + 3;
            pa0h[0] = pack_hi(sa[nfa][0], sa[nfa][1]);
            pa0h[1] = pack_hi(sa[nfa][2], sa[nfa][3]);
            pa0h[2] = pack_hi(sa[nfb][0], sa[nfb][1]);
            pa0h[3] = pack_hi(sa[nfb][2], sa[nfb][3]);
            pa0l[0] = pack_lo(sa[nfa][0], sa[nfa][1]);
            pa0l[1] = pack_lo(sa[nfa][2], sa[nfa][3]);
            pa0l[2] = pack_lo(sa[nfb][0], sa[nfb][1]);
            pa0l[3] = pack_lo(sa[nfb][2], sa[nfb][3]);
            pa1h[0] = pack_hi(sa[nfc][0], sa[nfc][1]);
            pa1h[1] = pack_hi(sa[nfc][2], sa[nfc][3]);
            pa1h[2] = pack_hi(sa[nfd][0], sa[nfd][1]);
            pa1h[3] = pack_hi(sa[nfd][2], sa[nfd][3]);
            pa1l[0] = pack_lo(sa[nfc][0], sa[nfc][1]);
            pa1l[1] = pack_lo(sa[nfc][2], sa[nfc][3]);
            pa1l[2] = pack_lo(sa[nfd][0], sa[nfd][1]);
            pa1l[3] = pack_lo(sa[nfd][2], sa[nfd][3]);
#pragma unroll
            for (int nd = 0; nd < 4; nd++) {
                uint32_t vh4[4], vl4[4];
                uint32_t vo = kb + 20480 + ((k0 + (ln >> 3) * 8 + (ln & 7)) * RSA + nd * 8) * 2;
                ldm_x4_t(vh4, vo);
                ldm_x4_t(vl4, vo + 10240);
                mma_bf16(oacc[nd], pa0h, vh4 + 0);
                mma_bf16(oacc[nd], pa1h, vh4 + 2);
                mma_bf16(oacc[nd], pa0h, vl4 + 0);
                mma_bf16(oacc[nd], pa1h, vl4 + 2);
                mma_bf16(oacc[nd], pa0l, vh4 + 0);
                mma_bf16(oacc[nd], pa1l, vh4 + 2);
            }
        }
        __syncthreads();
    }

    float inv0 = 1.0f / ls0, inv1 = 1.0f / ls1;
    size_t o0 = (size_t)(tok0 + n0) * 128 + h * 32;
    size_t o1 = (size_t)(tok0 + n1) * 128 + h * 32;
#pragma unroll
    for (int nd = 0; nd < 4; nd++) {
        int d = nd * 8 + mcb;
        float a0 = oacc[nd][0] * inv0, a1 = oacc[nd][1] * inv0;
        float b0 = oacc[nd][2] * inv1, b1 = oacc[nd][3] * inv1;
        __nv_bfloat16 h0, l0, h1, l1;
        split_bf(a0, h0, l0); split_bf(a1, h1, l1);
        __nv_bfloat162 hh; hh.x = h0; hh.y = h1;
        __nv_bfloat162 ll; ll.x = l0; ll.y = l1;
        *(__nv_bfloat162*)(Obf + o0 + d) = hh;
        *(__nv_bfloat162*)(Obf + OMK + o0 + d) = ll;
        split_bf(b0, h0, l0); split_bf(b1, h1, l1);
        hh.x = h0; hh.y = h1; ll.x = l0; ll.y = l1;
        *(__nv_bfloat162*)(Obf + o1 + d) = hh;
        *(__nv_bfloat162*)(Obf + OMK + o1 + d) = ll;
    }
}

// ---------------------------------------------------------------------------
// Stage-1 attention on tensor cores (unchanged).
// ---------------------------------------------------------------------------
#define ASQ 0
#define ASK 10240
#define ASV 20480
#define ASB 30720

__global__ void __launch_bounds__(128)
attn_small_tc(const __nv_bfloat16* __restrict__ QKVbf, const float* __restrict__ table,
              __nv_bfloat16* __restrict__ Obf) {
    __shared__ __align__(16) char sm1[31424];
    uint32_t sb = smem_u32(sm1);
    float* sT = (float*)(sm1 + ASB);

    int tid = threadIdx.x, wid = tid >> 5, ln = tid & 31;
    int bh = blockIdx.x, b = bh >> 2, h = bh & 3;
    const long long QMK = (long long)MTOK * 384;
    const long long OMK = (long long)MTOK * 128;
    long long tokb = (long long)b * 49;

    for (int i = tid; i < 169; i += 128) sT[i] = table[i * 4 + h];
#pragma unroll
    for (int i = tid; i < 1536; i += 128) {
        int tensor = i / 512;
        int pl = (i >> 8) & 1;
        int r = (i >> 2) & 63;
        int c4 = (i & 3) * 8;
        int rc = r < 49 ? r : 48;
        cpa16(sb + tensor * 10240 + pl * 5120 + (r * RSA + c4) * 2,
              QKVbf + pl * QMK + (tokb + rc) * 384 + tensor * 128 + h * 32 + c4);
    }
    CPA_COMMIT;
    CPA_WAIT(0);
    __syncthreads();

    uint32_t qh[2][4], ql[2][4];
#pragma unroll
    for (int ks = 0; ks < 2; ks++) {
        uint32_t ao = sb + ASQ + ((wid * 16 + (ln & 15)) * RSA + ks * 16 + (ln >> 4) * 8) * 2;
        ldm_x4(qh[ks], ao);
        ldm_x4(ql[ks], ao + 5120);
    }

    float sa[8][4];
#pragma unroll
    for (int nf = 0; nf < 8; nf++) {
        sa[nf][0] = sa[nf][1] = sa[nf][2] = sa[nf][3] = 0.f;
        uint32_t bh4[4], bl4[4];
        uint32_t bo = sb + ASK + ((nf * 8 + (ln & 7)) * RSA + (ln >> 3) * 8) * 2;
        ldm_x4(bh4, bo);
        ldm_x4(bl4, bo + 5120);
        mma_bf16(sa[nf], qh[0], bh4 + 0);
        mma_bf16(sa[nf], qh[1], bh4 + 2);
        mma_bf16(sa[nf], qh[0], bl4 + 0);
        mma_bf16(sa[nf], qh[1], bl4 + 2);
        mma_bf16(sa[nf], ql[0], bh4 + 0);
        mma_bf16(sa[nf], ql[1], bh4 + 2);
    }

    int n0 = wid * 16 + (ln >> 2);
    int n1 = n0 + 8;
    int n0c = n0 < 49 ? n0 : 48;
    int n1c = n1 < 49 ? n1 : 48;
    int i1a = n0c / 7, j1a = n0c % 7;
    int i1b = n1c / 7, j1b = n1c % 7;
    int mcb = 2 * (ln & 3);
    const float SC = 5.656854249492381f;

    float mx0 = -1e30f, mx1 = -1e30f;
#pragma unroll
    for (int nf = 0; nf < 8; nf++) {
        int mc = nf * 8 + mcb;
        float s0, s1, s2, s3;
        if (mc < 49) {
            int i2 = mc / 7, j2 = mc % 7;
            s0 = sa[nf][0] * SC + sT[(i1a - i2 + 6) * 13 + (j1a - j2 + 6)];
            s2 = sa[nf][2] * SC + sT[(i1b - i2 + 6) * 13 + (j1b - j2 + 6)];
        } else { s0 = -1e30f; s2 = -1e30f; }
        if (mc + 1 < 49) {
            int i2 = (mc + 1) / 7, j2 = (mc + 1) % 7;
            s1 = sa[nf][1] * SC + sT[(i1a - i2 + 6) * 13 + (j1a - j2 + 6)];
            s3 = sa[nf][3] * SC + sT[(i1b - i2 + 6) * 13 + (j1b - j2 + 6)];
        } else { s1 = -1e30f; s3 = -1e30f; }
        sa[nf][0] = s0; sa[nf][1] = s1; sa[nf][2] = s2; sa[nf][3] = s3;
        mx0 = fmaxf(mx0, fmaxf(s0, s1));
        mx1 = fmaxf(mx1, fmaxf(s2, s3));
    }
    mx0 = fmaxf(mx0, __shfl_xor_sync(0xffffffffu, mx0, 1));
    mx0 = fmaxf(mx0, __shfl_xor_sync(0xffffffffu, mx0, 2));
    mx1 = fmaxf(mx1, __shfl_xor_sync(0xffffffffu, mx1, 1));
    mx1 = fmaxf(mx1, __shfl_xor_sync(0xffffffffu, mx1, 2));

    float ls0 = 0.f, ls1 = 0.f;
#pragma unroll
    for (int nf = 0; nf < 8; nf++) {
        float p0 = __expf(sa[nf][0] - mx0);
        float p1 = __expf(sa[nf][1] - mx0);
        float p2 = __expf(sa[nf][2] - mx1);
        float p3 = __expf(sa[nf][3] - mx1);
        sa[nf][0] = p0; sa[nf][1] = p1; sa[nf][2] = p2; sa[nf][3] = p3;
        ls0 += p0 + p1; ls1 += p2 + p3;
    }
    ls0 += __shfl_xor_sync(0xffffffffu, ls0, 1);
    ls0 += __shfl_xor_sync(0xffffffffu, ls0, 2);
    ls1 += __shfl_xor_sync(0xffffffffu, ls1, 1);
    ls1 += __shfl_xor_sync(0xffffffffu, ls1, 2);

    float oacc[4][4];
#pragma unroll
    for (int i = 0; i < 4; i++)
#pragma unroll
        for (int j = 0; j < 4; j++) oacc[i][j] = 0.f;
#pragma unroll
    for (int ks2 = 0; ks2 < 2; ks2++) {
        int k0 = ks2 * 32;
        uint32_t pa0h[4], pa0l[4], pa1h[4], pa1l[4];
        int nfa = 4 * ks2, nfb = nfa + 1, nfc = nfa + 2, nfd = nfa + 3;
        pa0h[0] = pack_hi(sa[nfa][0], sa[nfa][1]);
        pa0h[1] = pack_hi(sa[nfa][2], sa[nfa][3]);
        pa0h[2] = pack_hi(sa[nfb][0], sa[nfb][1]);
        pa0h[3] = pack_hi(sa[nfb][2], sa[nfb][3]);
        pa0l[0] = pack_lo(sa[nfa][0], sa[nfa][1]);
        pa0l[1] = pack_lo(sa[nfa][2], sa[nfa][3]);
        pa0l[2] = pack_lo(sa[nfb][0], sa[nfb][1]);
        pa0l[3] = pack_lo(sa[nfb][2], sa[nfb][3]);
        pa1h[0] = pack_hi(sa[nfc][0], sa[nfc][1]);
        pa1h[1] = pack_hi(sa[nfc][2], sa[nfc][3]);
        pa1h[2] = pack_hi(sa[nfd][0], sa[nfd][1]);
        pa1h[3] = pack_hi(sa[nfd][2], sa[nfd][3]);
        pa1l[0] = pack_lo(sa[nfc][0], sa[nfc][1]);
        pa1l[1] = pack_lo(sa[nfc][2], sa[nfc][3]);
        pa1l[2] = pack_lo(sa[nfd][0], sa[nfd][1]);
        pa1l[3] = pack_lo(sa[nfd][2], sa[nfd][3]);
#pragma unroll
        for (int nd = 0; nd < 4; nd++) {
            uint32_t vh4[4], vl4[4];
            uint32_t vo = sb + ASV + ((k0 + (ln >> 3) * 8 + (ln & 7)) * RSA + nd * 8) * 2;
            ldm_x4_t(vh4, vo);
            ldm_x4_t(vl4, vo + 5120);
            mma_bf16(oacc[nd], pa0h, vh4 + 0);
            mma_bf16(oacc[nd], pa1h, vh4 + 2);
            mma_bf16(oacc[nd], pa0h, vl4 + 0);
            mma_bf16(oacc[nd], pa1h, vl4 + 2);
            mma_bf16(oacc[nd], pa0l, vh4 + 0);
            mma_bf16(oacc[nd], pa1l, vh4 + 2);
        }
    }

    float inv0 = 1.0f / ls0, inv1 = 1.0f / ls1;
#pragma unroll
    for (int nd = 0; nd < 4; nd++) {
        int d = nd * 8 + mcb;
        if (n0 < 49) {
            size_t o0 = (size_t)(tokb + n0) * 128 + h * 32 + d;
            __nv_bfloat16 h0, l0, h1, l1;
            split_bf(oacc[nd][0] * inv0, h0, l0);
            split_bf(oacc[nd][1] * inv0, h1, l1);
            __nv_bfloat162 hh; hh.x = h0; hh.y = h1;
            __nv_bfloat162 ll; ll.x = l0; ll.y = l1;
            *(__nv_bfloat162*)(Obf + o0) = hh;
            *(__nv_bfloat162*)(Obf + OMK + o0) = ll;
        }
        if (n1 < 49) {
            size_t o1 = (size_t)(tokb + n1) * 128 + h * 32 + d;
            __nv_bfloat16 h0, l0, h1, l1;
            split_bf(oacc[nd][2] * inv1, h0, l0);
            split_bf(oacc[nd][3] * inv1, h1, l1);
            __nv_bfloat162 hh; hh.x = h0; hh.y = h1;
            __nv_bfloat162 ll; ll.x = l0; ll.y = l1;
            *(__nv_bfloat162*)(Obf + o1) = hh;
            *(__nv_bfloat162*)(Obf + OMK + o1) = ll;
        }
    }
}

// ------------------------- permutations ------------------------------------
// window partition: write planes only.
__global__ void __launch_bounds__(256)
winpart_tile(const float* __restrict__ x, __nv_bfloat16* __restrict__ Xbf) {
    __shared__ float tile[32][65];
    const long long XMK = (long long)MTOK * 128;
    int sp0 = blockIdx.x * 64;
    int c0 = blockIdx.y * 32;
    int tid = threadIdx.x;
    {
        int ci = tid >> 3, si = (tid & 7) * 8;
        const float* p = x + (size_t)(c0 + ci) * MTOK + sp0 + si;
        float4 u0 = *(const float4*)p;
        float4 u1 = *(const float4*)(p + 4);
        tile[ci][si + 0] = u0.x; tile[ci][si + 1] = u0.y;
        tile[ci][si + 2] = u0.z; tile[ci][si + 3] = u0.w;
        tile[ci][si + 4] = u1.x; tile[ci][si + 5] = u1.y;
        tile[ci][si + 6] = u1.z; tile[ci][si + 7] = u1.w;
    }
    __syncthreads();
    {
        int si = tid >> 2, cj = (tid & 3) * 8;
        int sp = sp0 + si;
        int hh = sp / HWDIM, ww = sp % HWDIM;
        int out_t = ((hh / 7) * 32 + (ww / 7)) * 49 + (hh % 7) * 7 + (ww % 7);
        size_t ob = (size_t)out_t * 128 + c0 + cj;
#pragma unroll
        for (int k2 = 0; k2 < 4; k2++) {
            float v0 = tile[cj + 2 * k2][si];
            float v1 = tile[cj + 2 * k2 + 1][si];
            __nv_bfloat16 h0, l0, h1, l1;
            split_bf(v0, h0, l0);
            split_bf(v1, h1, l1);
            __nv_bfloat162 hh2; hh2.x = h0; hh2.y = h1;
            __nv_bfloat162 ll2; ll2.x = l0; ll2.y = l1;
            *(__nv_bfloat162*)(Xbf + ob + 2 * k2) = hh2;
            *(__nv_bfloat162*)(Xbf + XMK + ob + 2 * k2) = ll2;
        }
    }
}

// b2g permute: read bf16 planes (stage1 fc2 output in g_Obf), write Xbf planes.
__global__ void __launch_bounds__(256)
permute_b2g_tile(const __nv_bfloat16* __restrict__ A, __nv_bfloat16* __restrict__ Xbf) {
    __shared__ float tile[32][129];
    const long long XMK = (long long)MTOK * 128;
    int ho = blockIdx.x;
    int tok1 = blockIdx.y;
    int hi2 = tok1 / 7, wi2 = tok1 % 7;
    int tid = threadIdx.x;
    for (int i = tid; i < 1024; i += 256) {
        int wo = i >> 5, c4 = (i & 31) * 4;
        size_t off = ((size_t)((ho * 32 + wo) * 49 + tok1)) * 128 + c4;
        uint2 uh = *(const uint2*)(A + off);
        uint2 ul = *(const uint2*)(A + XMK + off);
        const unsigned short* hs = (const unsigned short*)&uh;
        const unsigned short* ls = (const unsigned short*)&ul;
#pragma unroll
        for (int k = 0; k < 4; k++) {
            tile[wo][c4 + k] = __bfloat162float(__ushort_as_bfloat16(hs[k])) +
                               __bfloat162float(__ushort_as_bfloat16(ls[k]));
        }
    }
    __syncthreads();
    for (int i = tid; i < 1024; i += 256) {
        int c = i & 127, w4 = (i >> 7) * 4;
        int f = (((c * 32 + ho) * 7 + hi2) * 7 + wi2) * 32;
        int cg = f & 127, s = f >> 7;
        int h2 = s / 224, w2 = s % 224;
        int dtok = ((h2 >> 5) * 7 + (w2 >> 5)) * 1024 + (h2 & 31) * 32 + (w2 & 31);
        size_t d0 = (size_t)dtok * 128 + cg + w4;
        float v0 = tile[w4 + 0][c], v1 = tile[w4 + 1][c];
        float v2 = tile[w4 + 2][c], v3 = tile[w4 + 3][c];
        uint2 ph, pl2;
        ph.x = pack_hi(v0, v1); ph.y = pack_hi(v2, v3);
        pl2.x = pack_lo(v0, v1); pl2.y = pack_lo(v2, v3);
        *(uint2*)(Xbf + d0) = ph;
        *(uint2*)(Xbf + XMK + d0) = pl2;
    }
}

__global__ void permute_g2out_kernel(const float* __restrict__ A, float* __restrict__ out) {
    int idx = (blockIdx.x * 256 + threadIdx.x) * 4;
    if (idx >= MTOK * CCH) return;
    float4 r;
    float* rp = (float*)&r;
#pragma unroll
    for (int k = 0; k < 4; k++) {
        int id = idx + k;
        int w2 = id % HWDIM;
        int t = id / HWDIM;
        int h2 = t % HWDIM;
        int c2 = t / HWDIM;
        int f = (h2 * HWDIM + w2) * CCH + c2;
        int gwo = f % 7;  f /= 7;
        int gwi = f & 31; f >>= 5;
        int ghi = f & 31; f >>= 5;
        int gho = f % 7;  f /= 7;
        int c = f;
        rp[k] = A[((size_t)((gho * 7 + gwo) * 1024 + ghi * 32 + gwi)) * 128 + c];
    }
    *(float4*)(out + idx) = r;
}

// ------------------------- weight pre-split ---------------------------------
struct WParams {
    const float* src[8];
    __nv_bfloat16* dst[8];
    int N[8];
    int K[8];
};
__global__ void convw8(WParams p) {
    int w = blockIdx.y;
    int N = p.N[w], K = p.K[w];
    int NK = N * K;
    const float* src = p.src[w];
    __nv_bfloat16* dst = p.dst[w];
    for (int idx = blockIdx.x * 256 + threadIdx.x; idx < NK; idx += gridDim.x * 256) {
        int n = idx / K, k = idx % K;
        float v = src[idx];
        __nv_bfloat16 h, l;
        split_bf(v, h, l);
        dst[(size_t)k * N + n] = h;
        dst[(size_t)NK + (size_t)k * N + n] = l;
    }
}

// ------------------------- host orchestration -------------------------------
extern "C" void kernel_launch(void* const* d_in, const int* in_sizes, int n_in,
                              void* d_out, int out_size) {
    const float* x = (const float*)d_in[0];
    const float* bp[10];
    const float* gp[10];
    for (int i = 0; i < 10; i++) bp[i] = (const float*)d_in[1 + i];
    for (int i = 0; i < 10; i++) gp[i] = (const float*)d_in[11 + i];

    cudaFuncSetAttribute(gemm_bf, cudaFuncAttributeMaxDynamicSharedMemorySize, GSMEM);
    cudaFuncSetAttribute(flash2, cudaFuncAttributeMaxDynamicSharedMemorySize, FSMEM);

    float* Out;
    __nv_bfloat16 *Xbf, *QKVbf, *Obf, *Ynbf, *Zbf, *Wbf;
    cudaGetSymbolAddress((void**)&Out, g_Out);
    cudaGetSymbolAddress((void**)&Xbf, g_Xbf);
    cudaGetSymbolAddress((void**)&QKVbf, g_QKVbf);
    cudaGetSymbolAddress((void**)&Obf, g_Obf);
    cudaGetSymbolAddress((void**)&Ynbf, g_Ynbf);
    cudaGetSymbolAddress((void**)&Zbf, g_Zbf);
    cudaGetSymbolAddress((void**)&Wbf, g_Wbf);

    const long long XMK = (long long)MTOK * 128;
    const long long QMK = (long long)MTOK * 384;
    const long long ZMK = (long long)MTOK * 512;

    WParams wp;
    wp.src[0] = bp[1]; wp.dst[0] = Wbf + 0;      wp.N[0] = 384; wp.K[0] = 128;
    wp.src[1] = bp[2]; wp.dst[1] = Wbf + 98304;  wp.N[1] = 128; wp.K[1] = 128;
    wp.src[2] = bp[6]; wp.dst[2] = Wbf + 131072; wp.N[2] = 512; wp.K[2] = 128;
    wp.src[3] = bp[8]; wp.dst[3] = Wbf + 262144; wp.N[3] = 128; wp.K[3] = 512;
    wp.src[4] = gp[1]; wp.dst[4] = Wbf + 393216; wp.N[4] = 384; wp.K[4] = 128;
    wp.src[5] = gp[2]; wp.dst[5] = Wbf + 491520; wp.N[5] = 128; wp.K[5] = 128;
    wp.src[6] = gp[6]; wp.dst[6] = Wbf + 524288; wp.N[6] = 512; wp.K[6] = 128;
    wp.src[7] = gp[8]; wp.dst[7] = Wbf + 655360; wp.N[7] = 128; wp.K[7] = 512;
    convw8<<<dim3(64, 8), 256>>>(wp);

    // ================= Stage 1: 7x7 windows ==================
    winpart_tile<<<dim3(MTOK / 64, 4), 256>>>(x, Xbf);
    gemm_bf<<<dim3(392, 3), 256, GSMEM>>>(Xbf, XMK, Wbf + 0, 49152, 128, 384,
                                          nullptr, nullptr, 0, nullptr, QKVbf, QMK, 1, nullptr, nullptr);
    attn_small_tc<<<4096, 128>>>(QKVbf, bp[0], Obf);
    gemm_bf<<<dim3(392, 1), 256, GSMEM>>>(Obf, XMK, Wbf + 98304, 16384, 128, 128,
                                          bp[3], Xbf, XMK, nullptr, Ynbf, XMK, 2, bp[4], bp[5]);
    gemm_bf<<<dim3(392, 4), 256, GSMEM>>>(Ynbf, XMK, Wbf + 131072, 65536, 128, 512,
                                          bp[7], nullptr, 0, nullptr, Zbf, ZMK, 1, nullptr, nullptr);
    gemm_bf<<<dim3(392, 1), 256, GSMEM>>>(Zbf, ZMK, Wbf + 262144, 65536, 512, 128,
                                          bp[9], Ynbf, XMK, nullptr, Obf, XMK, 3, nullptr, nullptr);

    permute_b2g_tile<<<dim3(32, 49), 256>>>(Obf, Xbf);

    // ================= Stage 2: 32x32 grid ===================
    gemm_bf<<<dim3(392, 3), 256, GSMEM>>>(Xbf, XMK, Wbf + 393216, 49152, 128, 384,
                                          nullptr, nullptr, 0, nullptr, QKVbf, QMK, 1, nullptr, nullptr);
    flash2<<<dim3(8, 196), 256, FSMEM>>>(QKVbf, gp[0], Obf);
    gemm_bf<<<dim3(392, 1), 256, GSMEM>>>(Obf, XMK, Wbf + 491520, 16384, 128, 128,
                                          gp[3], Xbf, XMK, nullptr, Ynbf, XMK, 2, gp[4], gp[5]);
    gemm_bf<<<dim3(392, 4), 256, GSMEM>>>(Ynbf, XMK, Wbf + 524288, 65536, 128, 512,
                                          gp[7], nullptr, 0, nullptr, Zbf, ZMK, 1, nullptr, nullptr);
    gemm_bf<<<dim3(392, 1), 256, GSMEM>>>(Zbf, ZMK, Wbf + 655360, 65536, 512, 128,
                                          gp[9], Ynbf, XMK, Out, nullptr, 0, 0, nullptr, nullptr);

    permute_g2out_kernel<<<MTOK * CCH / 1024, 256>>>(Out, (float*)d_out);
}

// round 13
// speedup vs baseline: 1.0768x; 1.0267x over previous
#include <cuda_runtime.h>
#include <cuda_bf16.h>
#include <stdint.h>

// ---------------------------------------------------------------------------
// MaxSA R13: fc1+fc2 fused into one kernel (Z lives in smem, never in HBM).
// Everything else identical to R12 best.
// ---------------------------------------------------------------------------

#define CCH   128
#define HWDIM 224
#define MTOK  50176

__device__ __align__(16) float g_Out[MTOK * CCH];
__device__ __align__(16) __nv_bfloat16 g_Xbf [2u * MTOK * CCH];
__device__ __align__(16) __nv_bfloat16 g_QKVbf[2u * MTOK * 384];
__device__ __align__(16) __nv_bfloat16 g_Obf [2u * MTOK * CCH];
__device__ __align__(16) __nv_bfloat16 g_Ynbf[2u * MTOK * CCH];
__device__ __align__(16) __nv_bfloat16 g_Wbf [786432];

// ------------------------- helpers -----------------------------------------
__device__ __forceinline__ uint32_t smem_u32(const void* p) {
    uint32_t a;
    asm("{ .reg .u64 t; cvta.to.shared.u64 t, %1; cvt.u32.u64 %0, t; }" : "=r"(a) : "l"(p));
    return a;
}
__device__ __forceinline__ void mma_bf16(float* c, const uint32_t* a, const uint32_t* b) {
    asm volatile(
        "mma.sync.aligned.m16n8k16.row.col.f32.bf16.bf16.f32 "
        "{%0,%1,%2,%3}, {%4,%5,%6,%7}, {%8,%9}, {%0,%1,%2,%3};"
        : "+f"(c[0]), "+f"(c[1]), "+f"(c[2]), "+f"(c[3])
        : "r"(a[0]), "r"(a[1]), "r"(a[2]), "r"(a[3]), "r"(b[0]), "r"(b[1]));
}
__device__ __forceinline__ void ldm_x4(uint32_t* r, uint32_t addr) {
    asm volatile("ldmatrix.sync.aligned.m8n8.x4.shared.b16 {%0,%1,%2,%3}, [%4];"
                 : "=r"(r[0]), "=r"(r[1]), "=r"(r[2]), "=r"(r[3]) : "r"(addr));
}
__device__ __forceinline__ void ldm_x4_t(uint32_t* r, uint32_t addr) {
    asm volatile("ldmatrix.sync.aligned.m8n8.x4.trans.shared.b16 {%0,%1,%2,%3}, [%4];"
                 : "=r"(r[0]), "=r"(r[1]), "=r"(r[2]), "=r"(r[3]) : "r"(addr));
}
__device__ __forceinline__ uint32_t pack_hi(float x, float y) {
    return (uint32_t)__bfloat16_as_ushort(__float2bfloat16(x)) |
           ((uint32_t)__bfloat16_as_ushort(__float2bfloat16(y)) << 16);
}
__device__ __forceinline__ uint32_t pack_lo(float x, float y) {
    float xh = __bfloat162float(__float2bfloat16(x));
    float yh = __bfloat162float(__float2bfloat16(y));
    return (uint32_t)__bfloat16_as_ushort(__float2bfloat16(x - xh)) |
           ((uint32_t)__bfloat16_as_ushort(__float2bfloat16(y - yh)) << 16);
}
__device__ __forceinline__ void split_bf(float v, __nv_bfloat16& h, __nv_bfloat16& l) {
    h = __float2bfloat16(v);
    l = __float2bfloat16(v - __bfloat162float(h));
}
__device__ __forceinline__ float2 rec2(const __nv_bfloat16* p, long long RMK, size_t o) {
    __nv_bfloat162 h = *(const __nv_bfloat162*)(p + o);
    __nv_bfloat162 l = *(const __nv_bfloat162*)(p + RMK + o);
    return make_float2(__bfloat162float(h.x) + __bfloat162float(l.x),
                       __bfloat162float(h.y) + __bfloat162float(l.y));
}
__device__ __forceinline__ void cpa16(uint32_t d, const void* s) {
    asm volatile("cp.async.ca.shared.global [%0], [%1], 16;"
                 :: "r"(d), "l"(__cvta_generic_to_global(s)) : "memory");
}
#define CPA_COMMIT asm volatile("cp.async.commit_group;" ::: "memory")
#define CPA_WAIT(n) asm volatile("cp.async.wait_group %0;" :: "n"(n) : "memory")

#define RSA 40
#define RSB 136
#define ASZ (128 * RSA * 2)
#define BSZ (32 * RSB * 2)
#define STG (2 * ASZ + 2 * BSZ)
#define GSMEM (2 * STG)

// ---------------------------------------------------------------------------
// Dense GEMM (qkv / proj+LN): unchanged from R12.
// mode 1: plane out (+bias). mode 2: fused LN (+bias, +res planes), plane out.
// ---------------------------------------------------------------------------
__global__ void __launch_bounds__(256, 2)
gemm_bf(const __nv_bfloat16* __restrict__ A, long long AMK,
        const __nv_bfloat16* __restrict__ Wt, long long WNK,
        int K, int N,
        const float* __restrict__ bias,
        const __nv_bfloat16* __restrict__ resbf, long long RMK,
        float* __restrict__ C, __nv_bfloat16* __restrict__ Cbf, long long CMK,
        int mode, const float* __restrict__ lng, const float* __restrict__ lnb) {
    extern __shared__ char sm[];
    uint32_t sb = smem_u32(sm);
    int tid = threadIdx.x, wid = tid >> 5, l = tid & 31;
    long long bm = (long long)blockIdx.x * 128;
    int bn = blockIdx.y * 128;
    int wm = (wid & 3) * 32, wn = (wid >> 2) * 64;
    int nc = K >> 5;

    auto load_tile = [&](int st, int cc) {
        int k0 = cc << 5;
        uint32_t base = sb + st * STG;
#pragma unroll
        for (int i = tid; i < 1024; i += 256) {
            int pl = i >> 9;
            int r = (i >> 2) & 127;
            int c4 = (i & 3) * 8;
            cpa16(base + pl * ASZ + (r * RSA + c4) * 2,
                  A + pl * AMK + (bm + r) * K + k0 + c4);
        }
#pragma unroll
        for (int i = tid; i < 1024; i += 256) {
            int pl = i >> 9;
            int r = (i >> 4) & 31;
            int c8 = (i & 15) * 8;
            cpa16(base + 2 * ASZ + pl * BSZ + (r * RSB + c8) * 2,
                  Wt + pl * WNK + (size_t)(k0 + r) * N + bn + c8);
        }
    };

    float acc[2][8][4];
#pragma unroll
    for (int a = 0; a < 2; a++)
#pragma unroll
        for (int b = 0; b < 8; b++)
#pragma unroll
            for (int c = 0; c < 4; c++) acc[a][b][c] = 0.f;

    load_tile(0, 0);
    CPA_COMMIT;
    for (int c = 0; c < nc; c++) {
        if (c + 1 < nc) {
            load_tile((c + 1) & 1, c + 1);
            CPA_COMMIT;
            CPA_WAIT(1);
        } else {
            CPA_WAIT(0);
        }
        __syncthreads();
        uint32_t base = sb + (c & 1) * STG;

        uint32_t ah[2][2][4], al[2][2][4];
#pragma unroll
        for (int ks = 0; ks < 2; ks++)
#pragma unroll
            for (int mi = 0; mi < 2; mi++) {
                uint32_t ao = base + ((wm + mi * 16 + (l & 15)) * RSA + ks * 16 + (l >> 4) * 8) * 2;
                ldm_x4(ah[ks][mi], ao);
                ldm_x4(al[ks][mi], ao + ASZ);
            }
#pragma unroll
        for (int nf = 0; nf < 8; nf++) {
            uint32_t bo = base + 2 * ASZ +
                          ((((l >> 3) * 8) + (l & 7)) * RSB + wn + nf * 8) * 2;
            uint32_t bh[4], bl[4];
            ldm_x4_t(bh, bo);
            ldm_x4_t(bl, bo + BSZ);
#pragma unroll
            for (int ks = 0; ks < 2; ks++)
#pragma unroll
                for (int mi = 0; mi < 2; mi++) {
                    mma_bf16(acc[mi][nf], ah[ks][mi], bh + ks * 2);
                    mma_bf16(acc[mi][nf], ah[ks][mi], bl + ks * 2);
                    mma_bf16(acc[mi][nf], al[ks][mi], bh + ks * 2);
                }
        }
        __syncthreads();
    }

    int r0 = wm + (l >> 2);
    if (mode == 2) {
        float* tile  = (float*)sm;
        float* ps    = (float*)(sm + 66048);
        float* mus   = (float*)(sm + 68096);
        float* rstds = (float*)(sm + 68608);
#pragma unroll
        for (int mi = 0; mi < 2; mi++)
#pragma unroll
            for (int half = 0; half < 2; half++) {
                int row = r0 + mi * 16 + half * 8;
#pragma unroll
                for (int nf = 0; nf < 8; nf++) {
                    int col = wn + (l & 3) * 2 + nf * 8;
                    size_t o = (size_t)(bm + row) * 128 + col;
                    float2 rr = rec2(resbf, RMK, o);
                    tile[row * 129 + col]     = acc[mi][nf][half * 2 + 0] + bias[col] + rr.x;
                    tile[row * 129 + col + 1] = acc[mi][nf][half * 2 + 1] + bias[col + 1] + rr.y;
                }
            }
        __syncthreads();
        {
            int row = tid & 127, hf = tid >> 7;
            float s = 0.f, q = 0.f;
#pragma unroll 8
            for (int c2 = 0; c2 < 64; c2++) {
                float v = tile[row * 129 + hf * 64 + c2];
                s += v;
                q += v * v;
            }
            ps[tid] = s;
            ps[256 + tid] = q;
        }
        __syncthreads();
        if (tid < 128) {
            float ss = ps[tid] + ps[tid + 128];
            float qq = ps[256 + tid] + ps[256 + tid + 128];
            float mu = ss * (1.0f / 128.0f);
            float var = qq * (1.0f / 128.0f) - mu * mu;
            mus[tid] = mu;
            rstds[tid] = rsqrtf(var + 1e-5f);
        }
        __syncthreads();
        for (int idx = tid; idx < 16384; idx += 256) {
            int r = idx >> 7, c2 = idx & 127;
            float val = (tile[r * 129 + c2] - mus[r]) * rstds[r] * lng[c2] + lnb[c2];
            size_t o = (size_t)(bm + r) * 128 + c2;
            __nv_bfloat16 h, lo2;
            split_bf(val, h, lo2);
            Cbf[o] = h;
            Cbf[CMK + o] = lo2;
        }
        return;
    }

    int cb = bn + wn + (l & 3) * 2;
#pragma unroll
    for (int mi = 0; mi < 2; mi++) {
#pragma unroll
        for (int half = 0; half < 2; half++) {
            long long row = bm + r0 + mi * 16 + half * 8;
#pragma unroll
            for (int nf = 0; nf < 8; nf++) {
                int col = cb + nf * 8;
                float v0 = acc[mi][nf][half * 2 + 0];
                float v1 = acc[mi][nf][half * 2 + 1];
                if (bias) { v0 += bias[col]; v1 += bias[col + 1]; }
                size_t o = (size_t)row * N + col;
                if (mode != 1 && resbf) {
                    float2 rr = rec2(resbf, RMK, o);
                    v0 += rr.x;
                    v1 += rr.y;
                }
                if (mode == 0) {
                    *(float2*)(C + o) = make_float2(v0, v1);
                } else {
                    __nv_bfloat16 h0, l0, h1, l1;
                    split_bf(v0, h0, l0);
                    split_bf(v1, h1, l1);
                    __nv_bfloat162 hh; hh.x = h0; hh.y = h1;
                    __nv_bfloat162 ll; ll.x = l0; ll.y = l1;
                    *(__nv_bfloat162*)(Cbf + o) = hh;
                    *(__nv_bfloat162*)(Cbf + CMK + o) = ll;
                }
            }
        }
    }
}

// ---------------------------------------------------------------------------
// Fused MLP: out = (Yn@W1t + b1) @ W2t + b2 + res.  Z lives in smem only.
// One 128-row tile per CTA; 4 Z-chunks of 128 cols; 1 CTA/SM (188 KB smem).
// mode 0: fp32 out.  mode 3: bf16-plane out.
// smem: [0, 2*STG) gemm1 stages; [ZOFF, +81920) Z planes (4 chunks x hi/lo);
//       [W2OFF, +34816) W2 B-stages.
// ---------------------------------------------------------------------------
#define ZOFF  (2 * STG)
#define ZLOFF 40960
#define W2OFF (ZOFF + 81920)
#define FMSMEM (W2OFF + 2 * 17408)

__global__ void __launch_bounds__(256, 1)
fused_mlp(const __nv_bfloat16* __restrict__ A, long long AMK,
          const __nv_bfloat16* __restrict__ W1t,
          const float* __restrict__ b1,
          const __nv_bfloat16* __restrict__ W2t,
          const float* __restrict__ b2,
          const __nv_bfloat16* __restrict__ resbf, long long RMK,
          float* __restrict__ C, __nv_bfloat16* __restrict__ Cbf, long long CMK,
          int mode) {
    extern __shared__ char sm[];
    uint32_t sb = smem_u32(sm);
    const long long W1NK = 65536, W2NK = 65536;
    int tid = threadIdx.x, wid = tid >> 5, l = tid & 31;
    long long bm = (long long)blockIdx.x * 128;
    int wm = (wid & 3) * 32, wn = (wid >> 2) * 64;

    float outacc[2][8][4];
#pragma unroll
    for (int a = 0; a < 2; a++)
#pragma unroll
        for (int b = 0; b < 8; b++)
#pragma unroll
            for (int c = 0; c < 4; c++) outacc[a][b][c] = 0.f;

    for (int nz = 0; nz < 4; nz++) {
        // ================= gemm1: zacc = Yn @ W1t[:, nz*128..] ==============
        float zacc[2][8][4];
#pragma unroll
        for (int a = 0; a < 2; a++)
#pragma unroll
            for (int b = 0; b < 8; b++)
#pragma unroll
                for (int c = 0; c < 4; c++) zacc[a][b][c] = 0.f;

        auto load1 = [&](int st, int cc) {
            int k0 = cc << 5;
            uint32_t base = sb + st * STG;
#pragma unroll
            for (int i = tid; i < 1024; i += 256) {
                int pl = i >> 9;
                int r = (i >> 2) & 127;
                int c4 = (i & 3) * 8;
                cpa16(base + pl * ASZ + (r * RSA + c4) * 2,
                      A + pl * AMK + (bm + r) * 128 + k0 + c4);
            }
#pragma unroll
            for (int i = tid; i < 1024; i += 256) {
                int pl = i >> 9;
                int r = (i >> 4) & 31;
                int c8 = (i & 15) * 8;
                cpa16(base + 2 * ASZ + pl * BSZ + (r * RSB + c8) * 2,
                      W1t + pl * W1NK + (size_t)(k0 + r) * 512 + nz * 128 + c8);
            }
            CPA_COMMIT;
        };
        load1(0, 0);
        for (int c = 0; c < 4; c++) {
            if (c + 1 < 4) { load1((c + 1) & 1, c + 1); CPA_WAIT(1); }
            else           { CPA_WAIT(0); }
            __syncthreads();
            uint32_t base = sb + (c & 1) * STG;
            uint32_t ah[2][2][4], al[2][2][4];
#pragma unroll
            for (int ks = 0; ks < 2; ks++)
#pragma unroll
                for (int mi = 0; mi < 2; mi++) {
                    uint32_t ao = base + ((wm + mi * 16 + (l & 15)) * RSA + ks * 16 + (l >> 4) * 8) * 2;
                    ldm_x4(ah[ks][mi], ao);
                    ldm_x4(al[ks][mi], ao + ASZ);
                }
#pragma unroll
            for (int nf = 0; nf < 8; nf++) {
                uint32_t bo = base + 2 * ASZ +
                              ((((l >> 3) * 8) + (l & 7)) * RSB + wn + nf * 8) * 2;
                uint32_t bh[4], bl[4];
                ldm_x4_t(bh, bo);
                ldm_x4_t(bl, bo + BSZ);
#pragma unroll
                for (int ks = 0; ks < 2; ks++)
#pragma unroll
                    for (int mi = 0; mi < 2; mi++) {
                        mma_bf16(zacc[mi][nf], ah[ks][mi], bh + ks * 2);
                        mma_bf16(zacc[mi][nf], ah[ks][mi], bl + ks * 2);
                        mma_bf16(zacc[mi][nf], al[ks][mi], bh + ks * 2);
                    }
            }
            __syncthreads();
        }

        // ---- prefetch first W2 chunk while storing Z to smem ----
        auto load2 = [&](int st, int k2) {
            uint32_t base = sb + W2OFF + st * 17408;
#pragma unroll
            for (int i = tid; i < 1024; i += 256) {
                int pl = i >> 9;
                int r = (i >> 4) & 31;
                int c8 = (i & 15) * 8;
                cpa16(base + pl * 8704 + (r * RSB + c8) * 2,
                      W2t + pl * W2NK + (size_t)(nz * 128 + k2 * 32 + r) * 128 + c8);
            }
            CPA_COMMIT;
        };
        load2(0, 0);

        // ---- bias b1 + store Z planes (A-layout, 4 k-chunks) ----
        {
            float b1v[8][2];
#pragma unroll
            for (int nf = 0; nf < 8; nf++) {
                int gc = nz * 128 + wn + nf * 8 + (l & 3) * 2;
                b1v[nf][0] = b1[gc];
                b1v[nf][1] = b1[gc + 1];
            }
#pragma unroll
            for (int mi = 0; mi < 2; mi++)
#pragma unroll
                for (int half = 0; half < 2; half++) {
                    int row = wm + mi * 16 + (l >> 2) + half * 8;
#pragma unroll
                    for (int nf = 0; nf < 8; nf++) {
                        int col = wn + nf * 8 + (l & 3) * 2;
                        float v0 = zacc[mi][nf][half * 2 + 0] + b1v[nf][0];
                        float v1 = zacc[mi][nf][half * 2 + 1] + b1v[nf][1];
                        uint32_t off = ZOFF + (col >> 5) * 10240 + (row * RSA + (col & 31)) * 2;
                        *(uint32_t*)(sm + off)         = pack_hi(v0, v1);
                        *(uint32_t*)(sm + off + ZLOFF) = pack_lo(v0, v1);
                    }
                }
        }

        // ================= gemm2: outacc += Zsmem @ W2t[nz*128.., :] ========
        for (int k2 = 0; k2 < 4; k2++) {
            if (k2 + 1 < 4) { load2((k2 + 1) & 1, k2 + 1); CPA_WAIT(1); }
            else            { CPA_WAIT(0); }
            __syncthreads();
            uint32_t za = sb + ZOFF + k2 * 10240;
            uint32_t wb = sb + W2OFF + (k2 & 1) * 17408;
            uint32_t ah[2][2][4], al[2][2][4];
#pragma unroll
            for (int ks = 0; ks < 2; ks++)
#pragma unroll
                for (int mi = 0; mi < 2; mi++) {
                    uint32_t ao = za + ((wm + mi * 16 + (l & 15)) * RSA + ks * 16 + (l >> 4) * 8) * 2;
                    ldm_x4(ah[ks][mi], ao);
                    ldm_x4(al[ks][mi], ao + ZLOFF);
                }
#pragma unroll
            for (int nf = 0; nf < 8; nf++) {
                uint32_t bo = wb + ((((l >> 3) * 8) + (l & 7)) * RSB + wn + nf * 8) * 2;
                uint32_t bh[4], bl[4];
                ldm_x4_t(bh, bo);
                ldm_x4_t(bl, bo + 8704);
#pragma unroll
                for (int ks = 0; ks < 2; ks++)
#pragma unroll
                    for (int mi = 0; mi < 2; mi++) {
                        mma_bf16(outacc[mi][nf], ah[ks][mi], bh + ks * 2);
                        mma_bf16(outacc[mi][nf], ah[ks][mi], bl + ks * 2);
                        mma_bf16(outacc[mi][nf], al[ks][mi], bh + ks * 2);
                    }
            }
            __syncthreads();
        }
    }

    // ================= epilogue: + b2 + res ==================
    int r0 = wm + (l >> 2);
    int cb = wn + (l & 3) * 2;
#pragma unroll
    for (int mi = 0; mi < 2; mi++) {
#pragma unroll
        for (int half = 0; half < 2; half++) {
            long long row = bm + r0 + mi * 16 + half * 8;
#pragma unroll
            for (int nf = 0; nf < 8; nf++) {
                int col = cb + nf * 8;
                float v0 = outacc[mi][nf][half * 2 + 0] + b2[col];
                float v1 = outacc[mi][nf][half * 2 + 1] + b2[col + 1];
                size_t o = (size_t)row * 128 + col;
                float2 rr = rec2(resbf, RMK, o);
                v0 += rr.x;
                v1 += rr.y;
                if (mode == 0) {
                    *(float2*)(C + o) = make_float2(v0, v1);
                } else {
                    __nv_bfloat16 h0, l0, h1, l1;
                    split_bf(v0, h0, l0);
                    split_bf(v1, h1, l1);
                    __nv_bfloat162 hh; hh.x = h0; hh.y = h1;
                    __nv_bfloat162 ll; ll.x = l0; ll.y = l1;
                    *(__nv_bfloat162*)(Cbf + o) = hh;
                    *(__nv_bfloat162*)(Cbf + CMK + o) = ll;
                }
            }
        }
    }
}

// ---------------------------------------------------------------------------
// Stage-2 flash attention (unchanged from R12).
// ---------------------------------------------------------------------------
#define FKV 20480
#define FBIAS 102400
#define FSMEM (102400 + 3969 * 2 + 14)

__global__ void __launch_bounds__(256, 2)
flash2(const __nv_bfloat16* __restrict__ QKVbf, const float* __restrict__ table,
       __nv_bfloat16* __restrict__ Obf) {
    extern __shared__ char fsm[];
    uint32_t sb = smem_u32(fsm);
    __nv_bfloat16* sBias = (__nv_bfloat16*)(fsm + FBIAS);

    int tid = threadIdx.x, wid = tid >> 5, ln = tid & 31;
    int bh = blockIdx.y, b = bh >> 2, h = bh & 3;
    int bq = blockIdx.x * 128;
    const long long QMK = (long long)MTOK * 384;
    const long long OMK = (long long)MTOK * 128;
    long long tok0 = (long long)b * 1024;

    for (int i = tid; i < 3969; i += 256) sBias[i] = __float2bfloat16(table[i * 4 + h]);

#pragma unroll
    for (int i = tid; i < 1024; i += 256) {
        int pl = i >> 9, r = (i >> 2) & 127, c4 = (i & 3) * 8;
        cpa16(sb + pl * 10240 + (r * RSA + c4) * 2,
              QKVbf + pl * QMK + (tok0 + bq + r) * 384 + h * 32 + c4);
    }
    CPA_COMMIT;

    auto load_kv = [&](int kt) {
        uint32_t kbase = sb + FKV + (kt & 1) * 40960;
#pragma unroll
        for (int i = tid; i < 2048; i += 256) {
            int tensor = i >> 10;
            int pl = (i >> 9) & 1;
            int r = (i >> 2) & 127, c4 = (i & 3) * 8;
            cpa16(kbase + tensor * 20480 + pl * 10240 + (r * RSA + c4) * 2,
                  QKVbf + pl * QMK + (tok0 + kt * 128 + r) * 384 + 128 + tensor * 128 + h * 32 + c4);
        }
        CPA_COMMIT;
    };
    load_kv(0);
    CPA_WAIT(1);
    __syncthreads();

    int rbase = wid * 16;
    uint32_t qh[2][4], ql[2][4];
#pragma unroll
    for (int ks = 0; ks < 2; ks++) {
        uint32_t ao = sb + ((rbase + (ln & 15)) * RSA + ks * 16 + (ln >> 4) * 8) * 2;
        ldm_x4(qh[ks], ao);
        ldm_x4(ql[ks], ao + 10240);
    }

    float oacc[4][4];
#pragma unroll
    for (int i = 0; i < 4; i++)
#pragma unroll
        for (int j = 0; j < 4; j++) oacc[i][j] = 0.f;
    float m0 = -1e30f, m1 = -1e30f, ls0 = 0.f, ls1 = 0.f;

    int n0 = bq + rbase + (ln >> 2);
    int n1 = n0 + 8;
    int i1a = n0 >> 5, j1a = n0 & 31;
    int i1b = n1 >> 5, j1b = n1 & 31;
    int mcb = 2 * (ln & 3);
    const float SC = 5.656854249492381f;

    for (int kt = 0; kt < 8; kt++) {
        if (kt + 1 < 8) {
            load_kv(kt + 1);
            CPA_WAIT(1);
        } else {
            CPA_WAIT(0);
        }
        __syncthreads();
        uint32_t kb = sb + FKV + (kt & 1) * 40960;

        float sa[16][4];
#pragma unroll
        for (int nf = 0; nf < 16; nf++) {
            sa[nf][0] = sa[nf][1] = sa[nf][2] = sa[nf][3] = 0.f;
            uint32_t bh4[4], bl4[4];
            uint32_t bo = kb + ((nf * 8 + (ln & 7)) * RSA + (ln >> 3) * 8) * 2;
            ldm_x4(bh4, bo);
            ldm_x4(bl4, bo + 10240);
            mma_bf16(sa[nf], qh[0], bh4 + 0);
            mma_bf16(sa[nf], qh[1], bh4 + 2);
            mma_bf16(sa[nf], qh[0], bl4 + 0);
            mma_bf16(sa[nf], qh[1], bl4 + 2);
            mma_bf16(sa[nf], ql[0], bh4 + 0);
            mma_bf16(sa[nf], ql[1], bh4 + 2);
        }

        float mx0 = -1e30f, mx1 = -1e30f;
#pragma unroll
        for (int nf = 0; nf < 16; nf++) {
            int mc = kt * 128 + nf * 8 + mcb;
            int i2a = mc >> 5, j2a = mc & 31;
            int i2b = (mc + 1) >> 5, j2b = (mc + 1) & 31;
            float s0 = sa[nf][0] * SC + __bfloat162float(sBias[(i1a - i2a + 31) * 63 + (j1a - j2a + 31)]);
            float s1 = sa[nf][1] * SC + __bfloat162float(sBias[(i1a - i2b + 31) * 63 + (j1a - j2b + 31)]);
            float s2 = sa[nf][2] * SC + __bfloat162float(sBias[(i1b - i2a + 31) * 63 + (j1b - j2a + 31)]);
            float s3 = sa[nf][3] * SC + __bfloat162float(sBias[(i1b - i2b + 31) * 63 + (j1b - j2b + 31)]);
            sa[nf][0] = s0; sa[nf][1] = s1; sa[nf][2] = s2; sa[nf][3] = s3;
            mx0 = fmaxf(mx0, fmaxf(s0, s1));
            mx1 = fmaxf(mx1, fmaxf(s2, s3));
        }
        mx0 = fmaxf(mx0, __shfl_xor_sync(0xffffffffu, mx0, 1));
        mx0 = fmaxf(mx0, __shfl_xor_sync(0xffffffffu, mx0, 2));
        mx1 = fmaxf(mx1, __shfl_xor_sync(0xffffffffu, mx1, 1));
        mx1 = fmaxf(mx1, __shfl_xor_sync(0xffffffffu, mx1, 2));
        float mn0 = fmaxf(m0, mx0), mn1 = fmaxf(m1, mx1);
        float f0 = __expf(m0 - mn0), f1 = __expf(m1 - mn1);

        float su0 = 0.f, su1 = 0.f;
#pragma unroll
        for (int nf = 0; nf < 16; nf++) {
            float p0 = __expf(sa[nf][0] - mn0);
            float p1 = __expf(sa[nf][1] - mn0);
            float p2 = __expf(sa[nf][2] - mn1);
            float p3 = __expf(sa[nf][3] - mn1);
            sa[nf][0] = p0; sa[nf][1] = p1; sa[nf][2] = p2; sa[nf][3] = p3;
            su0 += p0 + p1; su1 += p2 + p3;
        }
        su0 += __shfl_xor_sync(0xffffffffu, su0, 1);
        su0 += __shfl_xor_sync(0xffffffffu, su0, 2);
        su1 += __shfl_xor_sync(0xffffffffu, su1, 1);
        su1 += __shfl_xor_sync(0xffffffffu, su1, 2);
        ls0 = ls0 * f0 + su0;
        ls1 = ls1 * f1 + su1;
        m0 = mn0; m1 = mn1;

#pragma unroll
        for (int nd = 0; nd < 4; nd++) {
            oacc[nd][0] *= f0; oacc[nd][1] *= f0;
            oacc[nd][2] *= f1; oacc[nd][3] *= f1;
        }

#pragma unroll
        for (int ks2 = 0; ks2 < 4; ks2++) {
            int k0 = ks2 * 32;
            uint32_t pa0h[4], pa0l[4], pa1h[4], pa1l[4];
            int nfa = 4 * ks2, nfb = nfa + 1, nfc = nfa + 2, nfd = nfa + 3;
            pa0h[0] = pack_hi(sa[nfa][0], sa[nfa][1]);
            pa0h[1] = pack_hi(sa[nfa][2], sa[nfa][3]);
            pa0h[2] = pack_hi(sa[nfb][0], sa[nfb][1]);
            pa0h[3] = pack_hi(sa[nfb][2], sa[nfb][3]);
            pa0l[0] = pack_lo(sa[nfa][0], sa[nfa][1]);
            pa0l[1] = pack_lo(sa[nfa][2], sa[nfa][3]);
            pa0l[2] = pack_lo(sa[nfb][0], sa[nfb][1]);
            pa0l[3] = pack_lo(sa[nfb][2], sa[nfb][3]);
            pa1h[0] = pack_hi(sa[nfc][0], sa[nfc][1]);
            pa1h[1] = pack_hi(sa[nfc][2], sa[nfc][3]);
            pa1h[2] = pack_hi(sa[nfd][0], sa[nfd][1]);
            pa1h[3] = pack_hi(sa[nfd][2], sa[nfd][3]);
            pa1l[0] = pack_lo(sa[nfc][0], sa[nfc][1]);
            pa1l[1] = pack_lo(sa[nfc][2], sa[nfc][3]);
            pa1l[2] = pack_lo(sa[nfd][0], sa[nfd][1]);
            pa1l[3] = pack_lo(sa[nfd][2], sa[nfd][3]);
#pragma unroll
            for (int nd = 0; nd < 4; nd++) {
                uint32_t vh4[4], vl4[4];
                uint32_t vo = kb + 20480 + ((k0 + (ln >> 3) * 8 + (ln & 7)) * RSA + nd * 8) * 2;
                ldm_x4_t(vh4, vo);
                ldm_x4_t(vl4, vo + 10240);
                mma_bf16(oacc[nd], pa0h, vh4 + 0);
                mma_bf16(oacc[nd], pa1h, vh4 + 2);
                mma_bf16(oacc[nd], pa0h, vl4 + 0);
                mma_bf16(oacc[nd], pa1h, vl4 + 2);
                mma_bf16(oacc[nd], pa0l, vh4 + 0);
                mma_bf16(oacc[nd], pa1l, vh4 + 2);
            }
        }
        __syncthreads();
    }

    float inv0 = 1.0f / ls0, inv1 = 1.0f / ls1;
    size_t o0 = (size_t)(tok0 + n0) * 128 + h * 32;
    size_t o1 = (size_t)(tok0 + n1) * 128 + h * 32;
#pragma unroll
    for (int nd = 0; nd < 4; nd++) {
        int d = nd * 8 + mcb;
        float a0 = oacc[nd][0] * inv0, a1 = oacc[nd][1] * inv0;
        float b0 = oacc[nd][2] * inv1, b1v = oacc[nd][3] * inv1;
        __nv_bfloat16 h0, l0, h1, l1;
        split_bf(a0, h0, l0); split_bf(a1, h1, l1);
        __nv_bfloat162 hh; hh.x = h0; hh.y = h1;
        __nv_bfloat162 ll; ll.x = l0; ll.y = l1;
        *(__nv_bfloat162*)(Obf + o0 + d) = hh;
        *(__nv_bfloat162*)(Obf + OMK + o0 + d) = ll;
        split_bf(b0, h0, l0); split_bf(b1v, h1, l1);
        hh.x = h0; hh.y = h1; ll.x = l0; ll.y = l1;
        *(__nv_bfloat162*)(Obf + o1 + d) = hh;
        *(__nv_bfloat162*)(Obf + OMK + o1 + d) = ll;
    }
}

// ---------------------------------------------------------------------------
// Stage-1 attention on tensor cores (unchanged).
// ---------------------------------------------------------------------------
#define ASQ 0
#define ASK 10240
#define ASV 20480
#define ASB 30720

__global__ void __launch_bounds__(128)
attn_small_tc(const __nv_bfloat16* __restrict__ QKVbf, const float* __restrict__ table,
              __nv_bfloat16* __restrict__ Obf) {
    __shared__ __align__(16) char sm1[31424];
    uint32_t sb = smem_u32(sm1);
    float* sT = (float*)(sm1 + ASB);

    int tid = threadIdx.x, wid = tid >> 5, ln = tid & 31;
    int bh = blockIdx.x, b = bh >> 2, h = bh & 3;
    const long long QMK = (long long)MTOK * 384;
    const long long OMK = (long long)MTOK * 128;
    long long tokb = (long long)b * 49;

    for (int i = tid; i < 169; i += 128) sT[i] = table[i * 4 + h];
#pragma unroll
    for (int i = tid; i < 1536; i += 128) {
        int tensor = i / 512;
        int pl = (i >> 8) & 1;
        int r = (i >> 2) & 63;
        int c4 = (i & 3) * 8;
        int rc = r < 49 ? r : 48;
        cpa16(sb + tensor * 10240 + pl * 5120 + (r * RSA + c4) * 2,
              QKVbf + pl * QMK + (tokb + rc) * 384 + tensor * 128 + h * 32 + c4);
    }
    CPA_COMMIT;
    CPA_WAIT(0);
    __syncthreads();

    uint32_t qh[2][4], ql[2][4];
#pragma unroll
    for (int ks = 0; ks < 2; ks++) {
        uint32_t ao = sb + ASQ + ((wid * 16 + (ln & 15)) * RSA + ks * 16 + (ln >> 4) * 8) * 2;
        ldm_x4(qh[ks], ao);
        ldm_x4(ql[ks], ao + 5120);
    }

    float sa[8][4];
#pragma unroll
    for (int nf = 0; nf < 8; nf++) {
        sa[nf][0] = sa[nf][1] = sa[nf][2] = sa[nf][3] = 0.f;
        uint32_t bh4[4], bl4[4];
        uint32_t bo = sb + ASK + ((nf * 8 + (ln & 7)) * RSA + (ln >> 3) * 8) * 2;
        ldm_x4(bh4, bo);
        ldm_x4(bl4, bo + 5120);
        mma_bf16(sa[nf], qh[0], bh4 + 0);
        mma_bf16(sa[nf], qh[1], bh4 + 2);
        mma_bf16(sa[nf], qh[0], bl4 + 0);
        mma_bf16(sa[nf], qh[1], bl4 + 2);
        mma_bf16(sa[nf], ql[0], bh4 + 0);
        mma_bf16(sa[nf], ql[1], bh4 + 2);
    }

    int n0 = wid * 16 + (ln >> 2);
    int n1 = n0 + 8;
    int n0c = n0 < 49 ? n0 : 48;
    int n1c = n1 < 49 ? n1 : 48;
    int i1a = n0c / 7, j1a = n0c % 7;
    int i1b = n1c / 7, j1b = n1c % 7;
    int mcb = 2 * (ln & 3);
    const float SC = 5.656854249492381f;

    float mx0 = -1e30f, mx1 = -1e30f;
#pragma unroll
    for (int nf = 0; nf < 8; nf++) {
        int mc = nf * 8 + mcb;
        float s0, s1, s2, s3;
        if (mc < 49) {
            int i2 = mc / 7, j2 = mc % 7;
            s0 = sa[nf][0] * SC + sT[(i1a - i2 + 6) * 13 + (j1a - j2 + 6)];
            s2 = sa[nf][2] * SC + sT[(i1b - i2 + 6) * 13 + (j1b - j2 + 6)];
        } else { s0 = -1e30f; s2 = -1e30f; }
        if (mc + 1 < 49) {
            int i2 = (mc + 1) / 7, j2 = (mc + 1) % 7;
            s1 = sa[nf][1] * SC + sT[(i1a - i2 + 6) * 13 + (j1a - j2 + 6)];
            s3 = sa[nf][3] * SC + sT[(i1b - i2 + 6) * 13 + (j1b - j2 + 6)];
        } else { s1 = -1e30f; s3 = -1e30f; }
        sa[nf][0] = s0; sa[nf][1] = s1; sa[nf][2] = s2; sa[nf][3] = s3;
        mx0 = fmaxf(mx0, fmaxf(s0, s1));
        mx1 = fmaxf(mx1, fmaxf(s2, s3));
    }
    mx0 = fmaxf(mx0, __shfl_xor_sync(0xffffffffu, mx0, 1));
    mx0 = fmaxf(mx0, __shfl_xor_sync(0xffffffffu, mx0, 2));
    mx1 = fmaxf(mx1, __shfl_xor_sync(0xffffffffu, mx1, 1));
    mx1 = fmaxf(mx1, __shfl_xor_sync(0xffffffffu, mx1, 2));

    float ls0 = 0.f, ls1 = 0.f;
#pragma unroll
    for (int nf = 0; nf < 8; nf++) {
        float p0 = __expf(sa[nf][0] - mx0);
        float p1 = __expf(sa[nf][1] - mx0);
        float p2 = __expf(sa[nf][2] - mx1);
        float p3 = __expf(sa[nf][3] - mx1);
        sa[nf][0] = p0; sa[nf][1] = p1; sa[nf][2] = p2; sa[nf][3] = p3;
        ls0 += p0 + p1; ls1 += p2 + p3;
    }
    ls0 += __shfl_xor_sync(0xffffffffu, ls0, 1);
    ls0 += __shfl_xor_sync(0xffffffffu, ls0, 2);
    ls1 += __shfl_xor_sync(0xffffffffu, ls1, 1);
    ls1 += __shfl_xor_sync(0xffffffffu, ls1, 2);

    float oacc[4][4];
#pragma unroll
    for (int i = 0; i < 4; i++)
#pragma unroll
        for (int j = 0; j < 4; j++) oacc[i][j] = 0.f;
#pragma unroll
    for (int ks2 = 0; ks2 < 2; ks2++) {
        int k0 = ks2 * 32;
        uint32_t pa0h[4], pa0l[4], pa1h[4], pa1l[4];
        int nfa = 4 * ks2, nfb = nfa + 1, nfc = nfa + 2, nfd = nfa + 3;
        pa0h[0] = pack_hi(sa[nfa][0], sa[nfa][1]);
        pa0h[1] = pack_hi(sa[nfa][2], sa[nfa][3]);
        pa0h[2] = pack_hi(sa[nfb][0], sa[nfb][1]);
        pa0h[3] = pack_hi(sa[nfb][2], sa[nfb][3]);
        pa0l[0] = pack_lo(sa[nfa][0], sa[nfa][1]);
        pa0l[1] = pack_lo(sa[nfa][2], sa[nfa][3]);
        pa0l[2] = pack_lo(sa[nfb][0], sa[nfb][1]);
        pa0l[3] = pack_lo(sa[nfb][2], sa[nfb][3]);
        pa1h[0] = pack_hi(sa[nfc][0], sa[nfc][1]);
        pa1h[1] = pack_hi(sa[nfc][2], sa[nfc][3]);
        pa1h[2] = pack_hi(sa[nfd][0], sa[nfd][1]);
        pa1h[3] = pack_hi(sa[nfd][2], sa[nfd][3]);
        pa1l[0] = pack_lo(sa[nfc][0], sa[nfc][1]);
        pa1l[1] = pack_lo(sa[nfc][2], sa[nfc][3]);
        pa1l[2] = pack_lo(sa[nfd][0], sa[nfd][1]);
        pa1l[3] = pack_lo(sa[nfd][2], sa[nfd][3]);
#pragma unroll
        for (int nd = 0; nd < 4; nd++) {
            uint32_t vh4[4], vl4[4];
            uint32_t vo = sb + ASV + ((k0 + (ln >> 3) * 8 + (ln & 7)) * RSA + nd * 8) * 2;
            ldm_x4_t(vh4, vo);
            ldm_x4_t(vl4, vo + 5120);
            mma_bf16(oacc[nd], pa0h, vh4 + 0);
            mma_bf16(oacc[nd], pa1h, vh4 + 2);
            mma_bf16(oacc[nd], pa0h, vl4 + 0);
            mma_bf16(oacc[nd], pa1h, vl4 + 2);
            mma_bf16(oacc[nd], pa0l, vh4 + 0);
            mma_bf16(oacc[nd], pa1l, vh4 + 2);
        }
    }

    float inv0 = 1.0f / ls0, inv1 = 1.0f / ls1;
#pragma unroll
    for (int nd = 0; nd < 4; nd++) {
        int d = nd * 8 + mcb;
        if (n0 < 49) {
            size_t o0 = (size_t)(tokb + n0) * 128 + h * 32 + d;
            __nv_bfloat16 h0, l0, h1, l1;
            split_bf(oacc[nd][0] * inv0, h0, l0);
            split_bf(oacc[nd][1] * inv0, h1, l1);
            __nv_bfloat162 hh; hh.x = h0; hh.y = h1;
            __nv_bfloat162 ll; ll.x = l0; ll.y = l1;
            *(__nv_bfloat162*)(Obf + o0) = hh;
            *(__nv_bfloat162*)(Obf + OMK + o0) = ll;
        }
        if (n1 < 49) {
            size_t o1 = (size_t)(tokb + n1) * 128 + h * 32 + d;
            __nv_bfloat16 h0, l0, h1, l1;
            split_bf(oacc[nd][2] * inv1, h0, l0);
            split_bf(oacc[nd][3] * inv1, h1, l1);
            __nv_bfloat162 hh; hh.x = h0; hh.y = h1;
            __nv_bfloat162 ll; ll.x = l0; ll.y = l1;
            *(__nv_bfloat162*)(Obf + o1) = hh;
            *(__nv_bfloat162*)(Obf + OMK + o1) = ll;
        }
    }
}

// ------------------------- permutations ------------------------------------
__global__ void __launch_bounds__(256)
winpart_tile(const float* __restrict__ x, __nv_bfloat16* __restrict__ Xbf) {
    __shared__ float tile[32][65];
    const long long XMK = (long long)MTOK * 128;
    int sp0 = blockIdx.x * 64;
    int c0 = blockIdx.y * 32;
    int tid = threadIdx.x;
    {
        int ci = tid >> 3, si = (tid & 7) * 8;
        const float* p = x + (size_t)(c0 + ci) * MTOK + sp0 + si;
        float4 u0 = *(const float4*)p;
        float4 u1 = *(const float4*)(p + 4);
        tile[ci][si + 0] = u0.x; tile[ci][si + 1] = u0.y;
        tile[ci][si + 2] = u0.z; tile[ci][si + 3] = u0.w;
        tile[ci][si + 4] = u1.x; tile[ci][si + 5] = u1.y;
        tile[ci][si + 6] = u1.z; tile[ci][si + 7] = u1.w;
    }
    __syncthreads();
    {
        int si = tid >> 2, cj = (tid & 3) * 8;
        int sp = sp0 + si;
        int hh = sp / HWDIM, ww = sp % HWDIM;
        int out_t = ((hh / 7) * 32 + (ww / 7)) * 49 + (hh % 7) * 7 + (ww % 7);
        size_t ob = (size_t)out_t * 128 + c0 + cj;
#pragma unroll
        for (int k2 = 0; k2 < 4; k2++) {
            float v0 = tile[cj + 2 * k2][si];
            float v1 = tile[cj + 2 * k2 + 1][si];
            __nv_bfloat16 h0, l0, h1, l1;
            split_bf(v0, h0, l0);
            split_bf(v1, h1, l1);
            __nv_bfloat162 hh2; hh2.x = h0; hh2.y = h1;
            __nv_bfloat162 ll2; ll2.x = l0; ll2.y = l1;
            *(__nv_bfloat162*)(Xbf + ob + 2 * k2) = hh2;
            *(__nv_bfloat162*)(Xbf + XMK + ob + 2 * k2) = ll2;
        }
    }
}

__global__ void __launch_bounds__(256)
permute_b2g_tile(const __nv_bfloat16* __restrict__ A, __nv_bfloat16* __restrict__ Xbf) {
    __shared__ float tile[32][129];
    const long long XMK = (long long)MTOK * 128;
    int ho = blockIdx.x;
    int tok1 = blockIdx.y;
    int hi2 = tok1 / 7, wi2 = tok1 % 7;
    int tid = threadIdx.x;
    for (int i = tid; i < 1024; i += 256) {
        int wo = i >> 5, c4 = (i & 31) * 4;
        size_t off = ((size_t)((ho * 32 + wo) * 49 + tok1)) * 128 + c4;
        uint2 uh = *(const uint2*)(A + off);
        uint2 ul = *(const uint2*)(A + XMK + off);
        const unsigned short* hs = (const unsigned short*)&uh;
        const unsigned short* ls = (const unsigned short*)&ul;
#pragma unroll
        for (int k = 0; k < 4; k++) {
            tile[wo][c4 + k] = __bfloat162float(__ushort_as_bfloat16(hs[k])) +
                               __bfloat162float(__ushort_as_bfloat16(ls[k]));
        }
    }
    __syncthreads();
    for (int i = tid; i < 1024; i += 256) {
        int c = i & 127, w4 = (i >> 7) * 4;
        int f = (((c * 32 + ho) * 7 + hi2) * 7 + wi2) * 32;
        int cg = f & 127, s = f >> 7;
        int h2 = s / 224, w2 = s % 224;
        int dtok = ((h2 >> 5) * 7 + (w2 >> 5)) * 1024 + (h2 & 31) * 32 + (w2 & 31);
        size_t d0 = (size_t)dtok * 128 + cg + w4;
        float v0 = tile[w4 + 0][c], v1 = tile[w4 + 1][c];
        float v2 = tile[w4 + 2][c], v3 = tile[w4 + 3][c];
        uint2 ph, pl2;
        ph.x = pack_hi(v0, v1); ph.y = pack_hi(v2, v3);
        pl2.x = pack_lo(v0, v1); pl2.y = pack_lo(v2, v3);
        *(uint2*)(Xbf + d0) = ph;
        *(uint2*)(Xbf + XMK + d0) = pl2;
    }
}

__global__ void permute_g2out_kernel(const float* __restrict__ A, float* __restrict__ out) {
    int idx = (blockIdx.x * 256 + threadIdx.x) * 4;
    if (idx >= MTOK * CCH) return;
    float4 r;
    float* rp = (float*)&r;
#pragma unroll
    for (int k = 0; k < 4; k++) {
        int id = idx + k;
        int w2 = id % HWDIM;
        int t = id / HWDIM;
        int h2 = t % HWDIM;
        int c2 = t / HWDIM;
        int f = (h2 * HWDIM + w2) * CCH + c2;
        int gwo = f % 7;  f /= 7;
        int gwi = f & 31; f >>= 5;
        int ghi = f & 31; f >>= 5;
        int gho = f % 7;  f /= 7;
        int c = f;
        rp[k] = A[((size_t)((gho * 7 + gwo) * 1024 + ghi * 32 + gwi)) * 128 + c];
    }
    *(float4*)(out + idx) = r;
}

// ------------------------- weight pre-split ---------------------------------
struct WParams {
    const float* src[8];
    __nv_bfloat16* dst[8];
    int N[8];
    int K[8];
};
__global__ void convw8(WParams p) {
    int w = blockIdx.y;
    int N = p.N[w], K = p.K[w];
    int NK = N * K;
    const float* src = p.src[w];
    __nv_bfloat16* dst = p.dst[w];
    for (int idx = blockIdx.x * 256 + threadIdx.x; idx < NK; idx += gridDim.x * 256) {
        int n = idx / K, k = idx % K;
        float v = src[idx];
        __nv_bfloat16 h, l;
        split_bf(v, h, l);
        dst[(size_t)k * N + n] = h;
        dst[(size_t)NK + (size_t)k * N + n] = l;
    }
}

// ------------------------- host orchestration -------------------------------
extern "C" void kernel_launch(void* const* d_in, const int* in_sizes, int n_in,
                              void* d_out, int out_size) {
    const float* x = (const float*)d_in[0];
    const float* bp[10];
    const float* gp[10];
    for (int i = 0; i < 10; i++) bp[i] = (const float*)d_in[1 + i];
    for (int i = 0; i < 10; i++) gp[i] = (const float*)d_in[11 + i];

    cudaFuncSetAttribute(gemm_bf, cudaFuncAttributeMaxDynamicSharedMemorySize, GSMEM);
    cudaFuncSetAttribute(flash2, cudaFuncAttributeMaxDynamicSharedMemorySize, FSMEM);
    cudaFuncSetAttribute(fused_mlp, cudaFuncAttributeMaxDynamicSharedMemorySize, FMSMEM);

    float* Out;
    __nv_bfloat16 *Xbf, *QKVbf, *Obf, *Ynbf, *Wbf;
    cudaGetSymbolAddress((void**)&Out, g_Out);
    cudaGetSymbolAddress((void**)&Xbf, g_Xbf);
    cudaGetSymbolAddress((void**)&QKVbf, g_QKVbf);
    cudaGetSymbolAddress((void**)&Obf, g_Obf);
    cudaGetSymbolAddress((void**)&Ynbf, g_Ynbf);
    cudaGetSymbolAddress((void**)&Wbf, g_Wbf);

    const long long XMK = (long long)MTOK * 128;
    const long long QMK = (long long)MTOK * 384;

    WParams wp;
    wp.src[0] = bp[1]; wp.dst[0] = Wbf + 0;      wp.N[0] = 384; wp.K[0] = 128;
    wp.src[1] = bp[2]; wp.dst[1] = Wbf + 98304;  wp.N[1] = 128; wp.K[1] = 128;
    wp.src[2] = bp[6]; wp.dst[2] = Wbf + 131072; wp.N[2] = 512; wp.K[2] = 128;
    wp.src[3] = bp[8]; wp.dst[3] = Wbf + 262144; wp.N[3] = 128; wp.K[3] = 512;
    wp.src[4] = gp[1]; wp.dst[4] = Wbf + 393216; wp.N[4] = 384; wp.K[4] = 128;
    wp.src[5] = gp[2]; wp.dst[5] = Wbf + 491520; wp.N[5] = 128; wp.K[5] = 128;
    wp.src[6] = gp[6]; wp.dst[6] = Wbf + 524288; wp.N[6] = 512; wp.K[6] = 128;
    wp.src[7] = gp[8]; wp.dst[7] = Wbf + 655360; wp.N[7] = 128; wp.K[7] = 512;
    convw8<<<dim3(64, 8), 256>>>(wp);

    // ================= Stage 1: 7x7 windows ==================
    winpart_tile<<<dim3(MTOK / 64, 4), 256>>>(x, Xbf);
    gemm_bf<<<dim3(392, 3), 256, GSMEM>>>(Xbf, XMK, Wbf + 0, 49152, 128, 384,
                                          nullptr, nullptr, 0, nullptr, QKVbf, QMK, 1, nullptr, nullptr);
    attn_small_tc<<<4096, 128>>>(QKVbf, bp[0], Obf);
    gemm_bf<<<dim3(392, 1), 256, GSMEM>>>(Obf, XMK, Wbf + 98304, 16384, 128, 128,
                                          bp[3], Xbf, XMK, nullptr, Ynbf, XMK, 2, bp[4], bp[5]);
    fused_mlp<<<392, 256, FMSMEM>>>(Ynbf, XMK, Wbf + 131072, bp[7], Wbf + 262144, bp[9],
                                    Ynbf, XMK, nullptr, Obf, XMK, 3);

    permute_b2g_tile<<<dim3(32, 49), 256>>>(Obf, Xbf);

    // ================= Stage 2: 32x32 grid ===================
    gemm_bf<<<dim3(392, 3), 256, GSMEM>>>(Xbf, XMK, Wbf + 393216, 49152, 128, 384,
                                          nullptr, nullptr, 0, nullptr, QKVbf, QMK, 1, nullptr, nullptr);
    flash2<<<dim3(8, 196), 256, FSMEM>>>(QKVbf, gp[0], Obf);
    gemm_bf<<<dim3(392, 1), 256, GSMEM>>>(Obf, XMK, Wbf + 491520, 16384, 128, 128,
                                          gp[3], Xbf, XMK, nullptr, Ynbf, XMK, 2, gp[4], gp[5]);
    fused_mlp<<<392, 256, FMSMEM>>>(Ynbf, XMK, Wbf + 524288, gp[7], Wbf + 655360, gp[9],
                                    Ynbf, XMK, Out, nullptr, 0, 0);

    permute_g2out_kernel<<<MTOK * CCH / 1024, 256>>>(Out, (float*)d_out);
}

// round 14
// speedup vs baseline: 1.0784x; 1.0015x over previous
#include <cuda_runtime.h>
#include <cuda_bf16.h>
#include <stdint.h>

// ---------------------------------------------------------------------------
// MaxSA R14: n-tile fast-varying grid order in gemm_bf (same-A CTAs become
// schedule-adjacent -> A re-reads hit L2). Everything else identical to R13.
// ---------------------------------------------------------------------------

#define CCH   128
#define HWDIM 224
#define MTOK  50176

__device__ __align__(16) float g_Out[MTOK * CCH];
__device__ __align__(16) __nv_bfloat16 g_Xbf [2u * MTOK * CCH];
__device__ __align__(16) __nv_bfloat16 g_QKVbf[2u * MTOK * 384];
__device__ __align__(16) __nv_bfloat16 g_Obf [2u * MTOK * CCH];
__device__ __align__(16) __nv_bfloat16 g_Ynbf[2u * MTOK * CCH];
__device__ __align__(16) __nv_bfloat16 g_Wbf [786432];

// ------------------------- helpers -----------------------------------------
__device__ __forceinline__ uint32_t smem_u32(const void* p) {
    uint32_t a;
    asm("{ .reg .u64 t; cvta.to.shared.u64 t, %1; cvt.u32.u64 %0, t; }" : "=r"(a) : "l"(p));
    return a;
}
__device__ __forceinline__ void mma_bf16(float* c, const uint32_t* a, const uint32_t* b) {
    asm volatile(
        "mma.sync.aligned.m16n8k16.row.col.f32.bf16.bf16.f32 "
        "{%0,%1,%2,%3}, {%4,%5,%6,%7}, {%8,%9}, {%0,%1,%2,%3};"
        : "+f"(c[0]), "+f"(c[1]), "+f"(c[2]), "+f"(c[3])
        : "r"(a[0]), "r"(a[1]), "r"(a[2]), "r"(a[3]), "r"(b[0]), "r"(b[1]));
}
__device__ __forceinline__ void ldm_x4(uint32_t* r, uint32_t addr) {
    asm volatile("ldmatrix.sync.aligned.m8n8.x4.shared.b16 {%0,%1,%2,%3}, [%4];"
                 : "=r"(r[0]), "=r"(r[1]), "=r"(r[2]), "=r"(r[3]) : "r"(addr));
}
__device__ __forceinline__ void ldm_x4_t(uint32_t* r, uint32_t addr) {
    asm volatile("ldmatrix.sync.aligned.m8n8.x4.trans.shared.b16 {%0,%1,%2,%3}, [%4];"
                 : "=r"(r[0]), "=r"(r[1]), "=r"(r[2]), "=r"(r[3]) : "r"(addr));
}
__device__ __forceinline__ uint32_t pack_hi(float x, float y) {
    return (uint32_t)__bfloat16_as_ushort(__float2bfloat16(x)) |
           ((uint32_t)__bfloat16_as_ushort(__float2bfloat16(y)) << 16);
}
__device__ __forceinline__ uint32_t pack_lo(float x, float y) {
    float xh = __bfloat162float(__float2bfloat16(x));
    float yh = __bfloat162float(__float2bfloat16(y));
    return (uint32_t)__bfloat16_as_ushort(__float2bfloat16(x - xh)) |
           ((uint32_t)__bfloat16_as_ushort(__float2bfloat16(y - yh)) << 16);
}
__device__ __forceinline__ void split_bf(float v, __nv_bfloat16& h, __nv_bfloat16& l) {
    h = __float2bfloat16(v);
    l = __float2bfloat16(v - __bfloat162float(h));
}
__device__ __forceinline__ float2 rec2(const __nv_bfloat16* p, long long RMK, size_t o) {
    __nv_bfloat162 h = *(const __nv_bfloat162*)(p + o);
    __nv_bfloat162 l = *(const __nv_bfloat162*)(p + RMK + o);
    return make_float2(__bfloat162float(h.x) + __bfloat162float(l.x),
                       __bfloat162float(h.y) + __bfloat162float(l.y));
}
__device__ __forceinline__ void cpa16(uint32_t d, const void* s) {
    asm volatile("cp.async.ca.shared.global [%0], [%1], 16;"
                 :: "r"(d), "l"(__cvta_generic_to_global(s)) : "memory");
}
#define CPA_COMMIT asm volatile("cp.async.commit_group;" ::: "memory")
#define CPA_WAIT(n) asm volatile("cp.async.wait_group %0;" :: "n"(n) : "memory")

#define RSA 40
#define RSB 136
#define ASZ (128 * RSA * 2)
#define BSZ (32 * RSB * 2)
#define STG (2 * ASZ + 2 * BSZ)
#define GSMEM (2 * STG)

// ---------------------------------------------------------------------------
// Dense GEMM (qkv / proj+LN). n-tile = blockIdx.x (fast), m-tile = blockIdx.y.
// mode 1: plane out (+bias). mode 2: fused LN (+bias, +res planes), plane out.
// ---------------------------------------------------------------------------
__global__ void __launch_bounds__(256, 2)
gemm_bf(const __nv_bfloat16* __restrict__ A, long long AMK,
        const __nv_bfloat16* __restrict__ Wt, long long WNK,
        int K, int N,
        const float* __restrict__ bias,
        const __nv_bfloat16* __restrict__ resbf, long long RMK,
        float* __restrict__ C, __nv_bfloat16* __restrict__ Cbf, long long CMK,
        int mode, const float* __restrict__ lng, const float* __restrict__ lnb) {
    extern __shared__ char sm[];
    uint32_t sb = smem_u32(sm);
    int tid = threadIdx.x, wid = tid >> 5, l = tid & 31;
    long long bm = (long long)blockIdx.y * 128;   // m-tile: slow dim
    int bn = blockIdx.x * 128;                    // n-tile: fast dim (L2 reuse of A)
    int wm = (wid & 3) * 32, wn = (wid >> 2) * 64;
    int nc = K >> 5;

    auto load_tile = [&](int st, int cc) {
        int k0 = cc << 5;
        uint32_t base = sb + st * STG;
#pragma unroll
        for (int i = tid; i < 1024; i += 256) {
            int pl = i >> 9;
            int r = (i >> 2) & 127;
            int c4 = (i & 3) * 8;
            cpa16(base + pl * ASZ + (r * RSA + c4) * 2,
                  A + pl * AMK + (bm + r) * K + k0 + c4);
        }
#pragma unroll
        for (int i = tid; i < 1024; i += 256) {
            int pl = i >> 9;
            int r = (i >> 4) & 31;
            int c8 = (i & 15) * 8;
            cpa16(base + 2 * ASZ + pl * BSZ + (r * RSB + c8) * 2,
                  Wt + pl * WNK + (size_t)(k0 + r) * N + bn + c8);
        }
    };

    float acc[2][8][4];
#pragma unroll
    for (int a = 0; a < 2; a++)
#pragma unroll
        for (int b = 0; b < 8; b++)
#pragma unroll
            for (int c = 0; c < 4; c++) acc[a][b][c] = 0.f;

    load_tile(0, 0);
    CPA_COMMIT;
    for (int c = 0; c < nc; c++) {
        if (c + 1 < nc) {
            load_tile((c + 1) & 1, c + 1);
            CPA_COMMIT;
            CPA_WAIT(1);
        } else {
            CPA_WAIT(0);
        }
        __syncthreads();
        uint32_t base = sb + (c & 1) * STG;

        uint32_t ah[2][2][4], al[2][2][4];
#pragma unroll
        for (int ks = 0; ks < 2; ks++)
#pragma unroll
            for (int mi = 0; mi < 2; mi++) {
                uint32_t ao = base + ((wm + mi * 16 + (l & 15)) * RSA + ks * 16 + (l >> 4) * 8) * 2;
                ldm_x4(ah[ks][mi], ao);
                ldm_x4(al[ks][mi], ao + ASZ);
            }
#pragma unroll
        for (int nf = 0; nf < 8; nf++) {
            uint32_t bo = base + 2 * ASZ +
                          ((((l >> 3) * 8) + (l & 7)) * RSB + wn + nf * 8) * 2;
            uint32_t bh[4], bl[4];
            ldm_x4_t(bh, bo);
            ldm_x4_t(bl, bo + BSZ);
#pragma unroll
            for (int ks = 0; ks < 2; ks++)
#pragma unroll
                for (int mi = 0; mi < 2; mi++) {
                    mma_bf16(acc[mi][nf], ah[ks][mi], bh + ks * 2);
                    mma_bf16(acc[mi][nf], ah[ks][mi], bl + ks * 2);
                    mma_bf16(acc[mi][nf], al[ks][mi], bh + ks * 2);
                }
        }
        __syncthreads();
    }

    int r0 = wm + (l >> 2);
    if (mode == 2) {
        float* tile  = (float*)sm;
        float* ps    = (float*)(sm + 66048);
        float* mus   = (float*)(sm + 68096);
        float* rstds = (float*)(sm + 68608);
#pragma unroll
        for (int mi = 0; mi < 2; mi++)
#pragma unroll
            for (int half = 0; half < 2; half++) {
                int row = r0 + mi * 16 + half * 8;
#pragma unroll
                for (int nf = 0; nf < 8; nf++) {
                    int col = wn + (l & 3) * 2 + nf * 8;
                    size_t o = (size_t)(bm + row) * 128 + col;
                    float2 rr = rec2(resbf, RMK, o);
                    tile[row * 129 + col]     = acc[mi][nf][half * 2 + 0] + bias[col] + rr.x;
                    tile[row * 129 + col + 1] = acc[mi][nf][half * 2 + 1] + bias[col + 1] + rr.y;
                }
            }
        __syncthreads();
        {
            int row = tid & 127, hf = tid >> 7;
            float s = 0.f, q = 0.f;
#pragma unroll 8
            for (int c2 = 0; c2 < 64; c2++) {
                float v = tile[row * 129 + hf * 64 + c2];
                s += v;
                q += v * v;
            }
            ps[tid] = s;
            ps[256 + tid] = q;
        }
        __syncthreads();
        if (tid < 128) {
            float ss = ps[tid] + ps[tid + 128];
            float qq = ps[256 + tid] + ps[256 + tid + 128];
            float mu = ss * (1.0f / 128.0f);
            float var = qq * (1.0f / 128.0f) - mu * mu;
            mus[tid] = mu;
            rstds[tid] = rsqrtf(var + 1e-5f);
        }
        __syncthreads();
        for (int idx = tid; idx < 16384; idx += 256) {
            int r = idx >> 7, c2 = idx & 127;
            float val = (tile[r * 129 + c2] - mus[r]) * rstds[r] * lng[c2] + lnb[c2];
            size_t o = (size_t)(bm + r) * 128 + c2;
            __nv_bfloat16 h, lo2;
            split_bf(val, h, lo2);
            Cbf[o] = h;
            Cbf[CMK + o] = lo2;
        }
        return;
    }

    int cb = bn + wn + (l & 3) * 2;
#pragma unroll
    for (int mi = 0; mi < 2; mi++) {
#pragma unroll
        for (int half = 0; half < 2; half++) {
            long long row = bm + r0 + mi * 16 + half * 8;
#pragma unroll
            for (int nf = 0; nf < 8; nf++) {
                int col = cb + nf * 8;
                float v0 = acc[mi][nf][half * 2 + 0];
                float v1 = acc[mi][nf][half * 2 + 1];
                if (bias) { v0 += bias[col]; v1 += bias[col + 1]; }
                size_t o = (size_t)row * N + col;
                if (mode != 1 && resbf) {
                    float2 rr = rec2(resbf, RMK, o);
                    v0 += rr.x;
                    v1 += rr.y;
                }
                if (mode == 0) {
                    *(float2*)(C + o) = make_float2(v0, v1);
                } else {
                    __nv_bfloat16 h0, l0, h1, l1;
                    split_bf(v0, h0, l0);
                    split_bf(v1, h1, l1);
                    __nv_bfloat162 hh; hh.x = h0; hh.y = h1;
                    __nv_bfloat162 ll; ll.x = l0; ll.y = l1;
                    *(__nv_bfloat162*)(Cbf + o) = hh;
                    *(__nv_bfloat162*)(Cbf + CMK + o) = ll;
                }
            }
        }
    }
}

// ---------------------------------------------------------------------------
// Fused MLP (unchanged from R13): Z lives in smem only.
// ---------------------------------------------------------------------------
#define ZOFF  (2 * STG)
#define ZLOFF 40960
#define W2OFF (ZOFF + 81920)
#define FMSMEM (W2OFF + 2 * 17408)

__global__ void __launch_bounds__(256, 1)
fused_mlp(const __nv_bfloat16* __restrict__ A, long long AMK,
          const __nv_bfloat16* __restrict__ W1t,
          const float* __restrict__ b1,
          const __nv_bfloat16* __restrict__ W2t,
          const float* __restrict__ b2,
          const __nv_bfloat16* __restrict__ resbf, long long RMK,
          float* __restrict__ C, __nv_bfloat16* __restrict__ Cbf, long long CMK,
          int mode) {
    extern __shared__ char sm[];
    uint32_t sb = smem_u32(sm);
    const long long W1NK = 65536, W2NK = 65536;
    int tid = threadIdx.x, wid = tid >> 5, l = tid & 31;
    long long bm = (long long)blockIdx.x * 128;
    int wm = (wid & 3) * 32, wn = (wid >> 2) * 64;

    float outacc[2][8][4];
#pragma unroll
    for (int a = 0; a < 2; a++)
#pragma unroll
        for (int b = 0; b < 8; b++)
#pragma unroll
            for (int c = 0; c < 4; c++) outacc[a][b][c] = 0.f;

    for (int nz = 0; nz < 4; nz++) {
        float zacc[2][8][4];
#pragma unroll
        for (int a = 0; a < 2; a++)
#pragma unroll
            for (int b = 0; b < 8; b++)
#pragma unroll
                for (int c = 0; c < 4; c++) zacc[a][b][c] = 0.f;

        auto load1 = [&](int st, int cc) {
            int k0 = cc << 5;
            uint32_t base = sb + st * STG;
#pragma unroll
            for (int i = tid; i < 1024; i += 256) {
                int pl = i >> 9;
                int r = (i >> 2) & 127;
                int c4 = (i & 3) * 8;
                cpa16(base + pl * ASZ + (r * RSA + c4) * 2,
                      A + pl * AMK + (bm + r) * 128 + k0 + c4);
            }
#pragma unroll
            for (int i = tid; i < 1024; i += 256) {
                int pl = i >> 9;
                int r = (i >> 4) & 31;
                int c8 = (i & 15) * 8;
                cpa16(base + 2 * ASZ + pl * BSZ + (r * RSB + c8) * 2,
                      W1t + pl * W1NK + (size_t)(k0 + r) * 512 + nz * 128 + c8);
            }
            CPA_COMMIT;
        };
        load1(0, 0);
        for (int c = 0; c < 4; c++) {
            if (c + 1 < 4) { load1((c + 1) & 1, c + 1); CPA_WAIT(1); }
            else           { CPA_WAIT(0); }
            __syncthreads();
            uint32_t base = sb + (c & 1) * STG;
            uint32_t ah[2][2][4], al[2][2][4];
#pragma unroll
            for (int ks = 0; ks < 2; ks++)
#pragma unroll
                for (int mi = 0; mi < 2; mi++) {
                    uint32_t ao = base + ((wm + mi * 16 + (l & 15)) * RSA + ks * 16 + (l >> 4) * 8) * 2;
                    ldm_x4(ah[ks][mi], ao);
                    ldm_x4(al[ks][mi], ao + ASZ);
                }
#pragma unroll
            for (int nf = 0; nf < 8; nf++) {
                uint32_t bo = base + 2 * ASZ +
                              ((((l >> 3) * 8) + (l & 7)) * RSB + wn + nf * 8) * 2;
                uint32_t bh[4], bl[4];
                ldm_x4_t(bh, bo);
                ldm_x4_t(bl, bo + BSZ);
#pragma unroll
                for (int ks = 0; ks < 2; ks++)
#pragma unroll
                    for (int mi = 0; mi < 2; mi++) {
                        mma_bf16(zacc[mi][nf], ah[ks][mi], bh + ks * 2);
                        mma_bf16(zacc[mi][nf], ah[ks][mi], bl + ks * 2);
                        mma_bf16(zacc[mi][nf], al[ks][mi], bh + ks * 2);
                    }
            }
            __syncthreads();
        }

        auto load2 = [&](int st, int k2) {
            uint32_t base = sb + W2OFF + st * 17408;
#pragma unroll
            for (int i = tid; i < 1024; i += 256) {
                int pl = i >> 9;
                int r = (i >> 4) & 31;
                int c8 = (i & 15) * 8;
                cpa16(base + pl * 8704 + (r * RSB + c8) * 2,
                      W2t + pl * W2NK + (size_t)(nz * 128 + k2 * 32 + r) * 128 + c8);
            }
            CPA_COMMIT;
        };
        load2(0, 0);

        {
            float b1v[8][2];
#pragma unroll
            for (int nf = 0; nf < 8; nf++) {
                int gc = nz * 128 + wn + nf * 8 + (l & 3) * 2;
                b1v[nf][0] = b1[gc];
                b1v[nf][1] = b1[gc + 1];
            }
#pragma unroll
            for (int mi = 0; mi < 2; mi++)
#pragma unroll
                for (int half = 0; half < 2; half++) {
                    int row = wm + mi * 16 + (l >> 2) + half * 8;
#pragma unroll
                    for (int nf = 0; nf < 8; nf++) {
                        int col = wn + nf * 8 + (l & 3) * 2;
                        float v0 = zacc[mi][nf][half * 2 + 0] + b1v[nf][0];
                        float v1 = zacc[mi][nf][half * 2 + 1] + b1v[nf][1];
                        uint32_t off = ZOFF + (col >> 5) * 10240 + (row * RSA + (col & 31)) * 2;
                        *(uint32_t*)(sm + off)         = pack_hi(v0, v1);
                        *(uint32_t*)(sm + off + ZLOFF) = pack_lo(v0, v1);
                    }
                }
        }

        for (int k2 = 0; k2 < 4; k2++) {
            if (k2 + 1 < 4) { load2((k2 + 1) & 1, k2 + 1); CPA_WAIT(1); }
            else            { CPA_WAIT(0); }
            __syncthreads();
            uint32_t za = sb + ZOFF + k2 * 10240;
            uint32_t wb = sb + W2OFF + (k2 & 1) * 17408;
            uint32_t ah[2][2][4], al[2][2][4];
#pragma unroll
            for (int ks = 0; ks < 2; ks++)
#pragma unroll
                for (int mi = 0; mi < 2; mi++) {
                    uint32_t ao = za + ((wm + mi * 16 + (l & 15)) * RSA + ks * 16 + (l >> 4) * 8) * 2;
                    ldm_x4(ah[ks][mi], ao);
                    ldm_x4(al[ks][mi], ao + ZLOFF);
                }
#pragma unroll
            for (int nf = 0; nf < 8; nf++) {
                uint32_t bo = wb + ((((l >> 3) * 8) + (l & 7)) * RSB + wn + nf * 8) * 2;
                uint32_t bh[4], bl[4];
                ldm_x4_t(bh, bo);
                ldm_x4_t(bl, bo + 8704);
#pragma unroll
                for (int ks = 0; ks < 2; ks++)
#pragma unroll
                    for (int mi = 0; mi < 2; mi++) {
                        mma_bf16(outacc[mi][nf], ah[ks][mi], bh + ks * 2);
                        mma_bf16(outacc[mi][nf], ah[ks][mi], bl + ks * 2);
                        mma_bf16(outacc[mi][nf], al[ks][mi], bh + ks * 2);
                    }
            }
            __syncthreads();
        }
    }

    int r0 = wm + (l >> 2);
    int cb = wn + (l & 3) * 2;
#pragma unroll
    for (int mi = 0; mi < 2; mi++) {
#pragma unroll
        for (int half = 0; half < 2; half++) {
            long long row = bm + r0 + mi * 16 + half * 8;
#pragma unroll
            for (int nf = 0; nf < 8; nf++) {
                int col = cb + nf * 8;
                float v0 = outacc[mi][nf][half * 2 + 0] + b2[col];
                float v1 = outacc[mi][nf][half * 2 + 1] + b2[col + 1];
                size_t o = (size_t)row * 128 + col;
                float2 rr = rec2(resbf, RMK, o);
                v0 += rr.x;
                v1 += rr.y;
                if (mode == 0) {
                    *(float2*)(C + o) = make_float2(v0, v1);
                } else {
                    __nv_bfloat16 h0, l0, h1, l1;
                    split_bf(v0, h0, l0);
                    split_bf(v1, h1, l1);
                    __nv_bfloat162 hh; hh.x = h0; hh.y = h1;
                    __nv_bfloat162 ll; ll.x = l0; ll.y = l1;
                    *(__nv_bfloat162*)(Cbf + o) = hh;
                    *(__nv_bfloat162*)(Cbf + CMK + o) = ll;
                }
            }
        }
    }
}

// ---------------------------------------------------------------------------
// Stage-2 flash attention (unchanged from R13).
// ---------------------------------------------------------------------------
#define FKV 20480
#define FBIAS 102400
#define FSMEM (102400 + 3969 * 2 + 14)

__global__ void __launch_bounds__(256, 2)
flash2(const __nv_bfloat16* __restrict__ QKVbf, const float* __restrict__ table,
       __nv_bfloat16* __restrict__ Obf) {
    extern __shared__ char fsm[];
    uint32_t sb = smem_u32(fsm);
    __nv_bfloat16* sBias = (__nv_bfloat16*)(fsm + FBIAS);

    int tid = threadIdx.x, wid = tid >> 5, ln = tid & 31;
    int bh = blockIdx.y, b = bh >> 2, h = bh & 3;
    int bq = blockIdx.x * 128;
    const long long QMK = (long long)MTOK * 384;
    const long long OMK = (long long)MTOK * 128;
    long long tok0 = (long long)b * 1024;

    for (int i = tid; i < 3969; i += 256) sBias[i] = __float2bfloat16(table[i * 4 + h]);

#pragma unroll
    for (int i = tid; i < 1024; i += 256) {
        int pl = i >> 9, r = (i >> 2) & 127, c4 = (i & 3) * 8;
        cpa16(sb + pl * 10240 + (r * RSA + c4) * 2,
              QKVbf + pl * QMK + (tok0 + bq + r) * 384 + h * 32 + c4);
    }
    CPA_COMMIT;

    auto load_kv = [&](int kt) {
        uint32_t kbase = sb + FKV + (kt & 1) * 40960;
#pragma unroll
        for (int i = tid; i < 2048; i += 256) {
            int tensor = i >> 10;
            int pl = (i >> 9) & 1;
            int r = (i >> 2) & 127, c4 = (i & 3) * 8;
            cpa16(kbase + tensor * 20480 + pl * 10240 + (r * RSA + c4) * 2,
                  QKVbf + pl * QMK + (tok0 + kt * 128 + r) * 384 + 128 + tensor * 128 + h * 32 + c4);
        }
        CPA_COMMIT;
    };
    load_kv(0);
    CPA_WAIT(1);
    __syncthreads();

    int rbase = wid * 16;
    uint32_t qh[2][4], ql[2][4];
#pragma unroll
    for (int ks = 0; ks < 2; ks++) {
        uint32_t ao = sb + ((rbase + (ln & 15)) * RSA + ks * 16 + (ln >> 4) * 8) * 2;
        ldm_x4(qh[ks], ao);
        ldm_x4(ql[ks], ao + 10240);
    }

    float oacc[4][4];
#pragma unroll
    for (int i = 0; i < 4; i++)
#pragma unroll
        for (int j = 0; j < 4; j++) oacc[i][j] = 0.f;
    float m0 = -1e30f, m1 = -1e30f, ls0 = 0.f, ls1 = 0.f;

    int n0 = bq + rbase + (ln >> 2);
    int n1 = n0 + 8;
    int i1a = n0 >> 5, j1a = n0 & 31;
    int i1b = n1 >> 5, j1b = n1 & 31;
    int mcb = 2 * (ln & 3);
    const float SC = 5.656854249492381f;

    for (int kt = 0; kt < 8; kt++) {
        if (kt + 1 < 8) {
            load_kv(kt + 1);
            CPA_WAIT(1);
        } else {
            CPA_WAIT(0);
        }
        __syncthreads();
        uint32_t kb = sb + FKV + (kt & 1) * 40960;

        float sa[16][4];
#pragma unroll
        for (int nf = 0; nf < 16; nf++) {
            sa[nf][0] = sa[nf][1] = sa[nf][2] = sa[nf][3] = 0.f;
            uint32_t bh4[4], bl4[4];
            uint32_t bo = kb + ((nf * 8 + (ln & 7)) * RSA + (ln >> 3) * 8) * 2;
            ldm_x4(bh4, bo);
            ldm_x4(bl4, bo + 10240);
            mma_bf16(sa[nf], qh[0], bh4 + 0);
            mma_bf16(sa[nf], qh[1], bh4 + 2);
            mma_bf16(sa[nf], qh[0], bl4 + 0);
            mma_bf16(sa[nf], qh[1], bl4 + 2);
            mma_bf16(sa[nf], ql[0], bh4 + 0);
            mma_bf16(sa[nf], ql[1], bh4 + 2);
        }

        float mx0 = -1e30f, mx1 = -1e30f;
#pragma unroll
        for (int nf = 0; nf < 16; nf++) {
            int mc = kt * 128 + nf * 8 + mcb;
            int i2a = mc >> 5, j2a = mc & 31;
            int i2b = (mc + 1) >> 5, j2b = (mc + 1) & 31;
            float s0 = sa[nf][0] * SC + __bfloat162float(sBias[(i1a - i2a + 31) * 63 + (j1a - j2a + 31)]);
            float s1 = sa[nf][1] * SC + __bfloat162float(sBias[(i1a - i2b + 31) * 63 + (j1a - j2b + 31)]);
            float s2 = sa[nf][2] * SC + __bfloat162float(sBias[(i1b - i2a + 31) * 63 + (j1b - j2a + 31)]);
            float s3 = sa[nf][3] * SC + __bfloat162float(sBias[(i1b - i2b + 31) * 63 + (j1b - j2b + 31)]);
            sa[nf][0] = s0; sa[nf][1] = s1; sa[nf][2] = s2; sa[nf][3] = s3;
            mx0 = fmaxf(mx0, fmaxf(s0, s1));
            mx1 = fmaxf(mx1, fmaxf(s2, s3));
        }
        mx0 = fmaxf(mx0, __shfl_xor_sync(0xffffffffu, mx0, 1));
        mx0 = fmaxf(mx0, __shfl_xor_sync(0xffffffffu, mx0, 2));
        mx1 = fmaxf(mx1, __shfl_xor_sync(0xffffffffu, mx1, 1));
        mx1 = fmaxf(mx1, __shfl_xor_sync(0xffffffffu, mx1, 2));
        float mn0 = fmaxf(m0, mx0), mn1 = fmaxf(m1, mx1);
        float f0 = __expf(m0 - mn0), f1 = __expf(m1 - mn1);

        float su0 = 0.f, su1 = 0.f;
#pragma unroll
        for (int nf = 0; nf < 16; nf++) {
            float p0 = __expf(sa[nf][0] - mn0);
            float p1 = __expf(sa[nf][1] - mn0);
            float p2 = __expf(sa[nf][2] - mn1);
            float p3 = __expf(sa[nf][3] - mn1);
            sa[nf][0] = p0; sa[nf][1] = p1; sa[nf][2] = p2; sa[nf][3] = p3;
            su0 += p0 + p1; su1 += p2 + p3;
        }
        su0 += __shfl_xor_sync(0xffffffffu, su0, 1);
        su0 += __shfl_xor_sync(0xffffffffu, su0, 2);
        su1 += __shfl_xor_sync(0xffffffffu, su1, 1);
        su1 += __shfl_xor_sync(0xffffffffu, su1, 2);
        ls0 = ls0 * f0 + su0;
        ls1 = ls1 * f1 + su1;
        m0 = mn0; m1 = mn1;

#pragma unroll
        for (int nd = 0; nd < 4; nd++) {
            oacc[nd][0] *= f0; oacc[nd][1] *= f0;
            oacc[nd][2] *= f1; oacc[nd][3] *= f1;
        }

#pragma unroll
        for (int ks2 = 0; ks2 < 4; ks2++) {
            int k0 = ks2 * 32;
            uint32_t pa0h[4], pa0l[4], pa1h[4], pa1l[4];
            int nfa = 4 * ks2, nfb = nfa + 1, nfc = nfa + 2, nfd = nfa + 3;
            pa0h[0] = pack_hi(sa[nfa][0], sa[nfa][1]);
            pa0h[1] = pack_hi(sa[nfa][2], sa[nfa][3]);
            pa0h[2] = pack_hi(sa[nfb][0], sa[nfb][1]);
            pa0h[3] = pack_hi(sa[nfb][2], sa[nfb][3]);
            pa0l[0] = pack_lo(sa[nfa][0], sa[nfa][1]);
            pa0l[1] = pack_lo(sa[nfa][2], sa[nfa][3]);
            pa0l[2] = pack_lo(sa[nfb][0], sa[nfb][1]);
            pa0l[3] = pack_lo(sa[nfb][2], sa[nfb][3]);
            pa1h[0] = pack_hi(sa[nfc][0], sa[nfc][1]);
            pa1h[1] = pack_hi(sa[nfc][2], sa[nfc][3]);
            pa1h[2] = pack_hi(sa[nfd][0], sa[nfd][1]);
            pa1h[3] = pack_hi(sa[nfd][2], sa[nfd][3]);
            pa1l[0] = pack_lo(sa[nfc][0], sa[nfc][1]);
            pa1l[1] = pack_lo(sa[nfc][2], sa[nfc][3]);
            pa1l[2] = pack_lo(sa[nfd][0], sa[nfd][1]);
            pa1l[3] = pack_lo(sa[nfd][2], sa[nfd][3]);
#pragma unroll
            for (int nd = 0; nd < 4; nd++) {
                uint32_t vh4[4], vl4[4];
                uint32_t vo = kb + 20480 + ((k0 + (ln >> 3) * 8 + (ln & 7)) * RSA + nd * 8) * 2;
                ldm_x4_t(vh4, vo);
                ldm_x4_t(vl4, vo + 10240);
                mma_bf16(oacc[nd], pa0h, vh4 + 0);
                mma_bf16(oacc[nd], pa1h, vh4 + 2);
                mma_bf16(oacc[nd], pa0h, vl4 + 0);
                mma_bf16(oacc[nd], pa1h, vl4 + 2);
                mma_bf16(oacc[nd], pa0l, vh4 + 0);
                mma_bf16(oacc[nd], pa1l, vh4 + 2);
            }
        }
        __syncthreads();
    }

    float inv0 = 1.0f / ls0, inv1 = 1.0f / ls1;
    size_t o0 = (size_t)(tok0 + n0) * 128 + h * 32;
    size_t o1 = (size_t)(tok0 + n1) * 128 + h * 32;
#pragma unroll
    for (int nd = 0; nd < 4; nd++) {
        int d = nd * 8 + mcb;
        float a0 = oacc[nd][0] * inv0, a1 = oacc[nd][1] * inv0;
        float b0 = oacc[nd][2] * inv1, b1v = oacc[nd][3] * inv1;
        __nv_bfloat16 h0, l0, h1, l1;
        split_bf(a0, h0, l0); split_bf(a1, h1, l1);
        __nv_bfloat162 hh; hh.x = h0; hh.y = h1;
        __nv_bfloat162 ll; ll.x = l0; ll.y = l1;
        *(__nv_bfloat162*)(Obf + o0 + d) = hh;
        *(__nv_bfloat162*)(Obf + OMK + o0 + d) = ll;
        split_bf(b0, h0, l0); split_bf(b1v, h1, l1);
        hh.x = h0; hh.y = h1; ll.x = l0; ll.y = l1;
        *(__nv_bfloat162*)(Obf + o1 + d) = hh;
        *(__nv_bfloat162*)(Obf + OMK + o1 + d) = ll;
    }
}

// ---------------------------------------------------------------------------
// Stage-1 attention on tensor cores (unchanged).
// ---------------------------------------------------------------------------
#define ASQ 0
#define ASK 10240
#define ASV 20480
#define ASB 30720

__global__ void __launch_bounds__(128)
attn_small_tc(const __nv_bfloat16* __restrict__ QKVbf, const float* __restrict__ table,
              __nv_bfloat16* __restrict__ Obf) {
    __shared__ __align__(16) char sm1[31424];
    uint32_t sb = smem_u32(sm1);
    float* sT = (float*)(sm1 + ASB);

    int tid = threadIdx.x, wid = tid >> 5, ln = tid & 31;
    int bh = blockIdx.x, b = bh >> 2, h = bh & 3;
    const long long QMK = (long long)MTOK * 384;
    const long long OMK = (long long)MTOK * 128;
    long long tokb = (long long)b * 49;

    for (int i = tid; i < 169; i += 128) sT[i] = table[i * 4 + h];
#pragma unroll
    for (int i = tid; i < 1536; i += 128) {
        int tensor = i / 512;
        int pl = (i >> 8) & 1;
        int r = (i >> 2) & 63;
        int c4 = (i & 3) * 8;
        int rc = r < 49 ? r : 48;
        cpa16(sb + tensor * 10240 + pl * 5120 + (r * RSA + c4) * 2,
              QKVbf + pl * QMK + (tokb + rc) * 384 + tensor * 128 + h * 32 + c4);
    }
    CPA_COMMIT;
    CPA_WAIT(0);
    __syncthreads();

    uint32_t qh[2][4], ql[2][4];
#pragma unroll
    for (int ks = 0; ks < 2; ks++) {
        uint32_t ao = sb + ASQ + ((wid * 16 + (ln & 15)) * RSA + ks * 16 + (ln >> 4) * 8) * 2;
        ldm_x4(qh[ks], ao);
        ldm_x4(ql[ks], ao + 5120);
    }

    float sa[8][4];
#pragma unroll
    for (int nf = 0; nf < 8; nf++) {
        sa[nf][0] = sa[nf][1] = sa[nf][2] = sa[nf][3] = 0.f;
        uint32_t bh4[4], bl4[4];
        uint32_t bo = sb + ASK + ((nf * 8 + (ln & 7)) * RSA + (ln >> 3) * 8) * 2;
        ldm_x4(bh4, bo);
        ldm_x4(bl4, bo + 5120);
        mma_bf16(sa[nf], qh[0], bh4 + 0);
        mma_bf16(sa[nf], qh[1], bh4 + 2);
        mma_bf16(sa[nf], qh[0], bl4 + 0);
        mma_bf16(sa[nf], qh[1], bl4 + 2);
        mma_bf16(sa[nf], ql[0], bh4 + 0);
        mma_bf16(sa[nf], ql[1], bh4 + 2);
    }

    int n0 = wid * 16 + (ln >> 2);
    int n1 = n0 + 8;
    int n0c = n0 < 49 ? n0 : 48;
    int n1c = n1 < 49 ? n1 : 48;
    int i1a = n0c / 7, j1a = n0c % 7;
    int i1b = n1c / 7, j1b = n1c % 7;
    int mcb = 2 * (ln & 3);
    const float SC = 5.656854249492381f;

    float mx0 = -1e30f, mx1 = -1e30f;
#pragma unroll
    for (int nf = 0; nf < 8; nf++) {
        int mc = nf * 8 + mcb;
        float s0, s1, s2, s3;
        if (mc < 49) {
            int i2 = mc / 7, j2 = mc % 7;
            s0 = sa[nf][0] * SC + sT[(i1a - i2 + 6) * 13 + (j1a - j2 + 6)];
            s2 = sa[nf][2] * SC + sT[(i1b - i2 + 6) * 13 + (j1b - j2 + 6)];
        } else { s0 = -1e30f; s2 = -1e30f; }
        if (mc + 1 < 49) {
            int i2 = (mc + 1) / 7, j2 = (mc + 1) % 7;
            s1 = sa[nf][1] * SC + sT[(i1a - i2 + 6) * 13 + (j1a - j2 + 6)];
            s3 = sa[nf][3] * SC + sT[(i1b - i2 + 6) * 13 + (j1b - j2 + 6)];
        } else { s1 = -1e30f; s3 = -1e30f; }
        sa[nf][0] = s0; sa[nf][1] = s1; sa[nf][2] = s2; sa[nf][3] = s3;
        mx0 = fmaxf(mx0, fmaxf(s0, s1));
        mx1 = fmaxf(mx1, fmaxf(s2, s3));
    }
    mx0 = fmaxf(mx0, __shfl_xor_sync(0xffffffffu, mx0, 1));
    mx0 = fmaxf(mx0, __shfl_xor_sync(0xffffffffu, mx0, 2));
    mx1 = fmaxf(mx1, __shfl_xor_sync(0xffffffffu, mx1, 1));
    mx1 = fmaxf(mx1, __shfl_xor_sync(0xffffffffu, mx1, 2));

    float ls0 = 0.f, ls1 = 0.f;
#pragma unroll
    for (int nf = 0; nf < 8; nf++) {
        float p0 = __expf(sa[nf][0] - mx0);
        float p1 = __expf(sa[nf][1] - mx0);
        float p2 = __expf(sa[nf][2] - mx1);
        float p3 = __expf(sa[nf][3] - mx1);
        sa[nf][0] = p0; sa[nf][1] = p1; sa[nf][2] = p2; sa[nf][3] = p3;
        ls0 += p0 + p1; ls1 += p2 + p3;
    }
    ls0 += __shfl_xor_sync(0xffffffffu, ls0, 1);
    ls0 += __shfl_xor_sync(0xffffffffu, ls0, 2);
    ls1 += __shfl_xor_sync(0xffffffffu, ls1, 1);
    ls1 += __shfl_xor_sync(0xffffffffu, ls1, 2);

    float oacc[4][4];
#pragma unroll
    for (int i = 0; i < 4; i++)
#pragma unroll
        for (int j = 0; j < 4; j++) oacc[i][j] = 0.f;
#pragma unroll
    for (int ks2 = 0; ks2 < 2; ks2++) {
        int k0 = ks2 * 32;
        uint32_t pa0h[4], pa0l[4], pa1h[4], pa1l[4];
        int nfa = 4 * ks2, nfb = nfa + 1, nfc = nfa + 2, nfd = nfa + 3;
        pa0h[0] = pack_hi(sa[nfa][0], sa[nfa][1]);
        pa0h[1] = pack_hi(sa[nfa][2], sa[nfa][3]);
        pa0h[2] = pack_hi(sa[nfb][0], sa[nfb][1]);
        pa0h[3] = pack_hi(sa[nfb][2], sa[nfb][3]);
        pa0l[0] = pack_lo(sa[nfa][0], sa[nfa][1]);
        pa0l[1] = pack_lo(sa[nfa][2], sa[nfa][3]);
        pa0l[2] = pack_lo(sa[nfb][0], sa[nfb][1]);
        pa0l[3] = pack_lo(sa[nfb][2], sa[nfb][3]);
        pa1h[0] = pack_hi(sa[nfc][0], sa[nfc][1]);
        pa1h[1] = pack_hi(sa[nfc][2], sa[nfc][3]);
        pa1h[2] = pack_hi(sa[nfd][0], sa[nfd][1]);
        pa1h[3] = pack_hi(sa[nfd][2], sa[nfd][3]);
        pa1l[0] = pack_lo(sa[nfc][0], sa[nfc][1]);
        pa1l[1] = pack_lo(sa[nfc][2], sa[nfc][3]);
        pa1l[2] = pack_lo(sa[nfd][0], sa[nfd][1]);
        pa1l[3] = pack_lo(sa[nfd][2], sa[nfd][3]);
#pragma unroll
        for (int nd = 0; nd < 4; nd++) {
            uint32_t vh4[4], vl4[4];
            uint32_t vo = sb + ASV + ((k0 + (ln >> 3) * 8 + (ln & 7)) * RSA + nd * 8) * 2;
            ldm_x4_t(vh4, vo);
            ldm_x4_t(vl4, vo + 5120);
            mma_bf16(oacc[nd], pa0h, vh4 + 0);
            mma_bf16(oacc[nd], pa1h, vh4 + 2);
            mma_bf16(oacc[nd], pa0h, vl4 + 0);
            mma_bf16(oacc[nd], pa1h, vl4 + 2);
            mma_bf16(oacc[nd], pa0l, vh4 + 0);
            mma_bf16(oacc[nd], pa1l, vh4 + 2);
        }
    }

    float inv0 = 1.0f / ls0, inv1 = 1.0f / ls1;
#pragma unroll
    for (int nd = 0; nd < 4; nd++) {
        int d = nd * 8 + mcb;
        if (n0 < 49) {
            size_t o0 = (size_t)(tokb + n0) * 128 + h * 32 + d;
            __nv_bfloat16 h0, l0, h1, l1;
            split_bf(oacc[nd][0] * inv0, h0, l0);
            split_bf(oacc[nd][1] * inv0, h1, l1);
            __nv_bfloat162 hh; hh.x = h0; hh.y = h1;
            __nv_bfloat162 ll; ll.x = l0; ll.y = l1;
            *(__nv_bfloat162*)(Obf + o0) = hh;
            *(__nv_bfloat162*)(Obf + OMK + o0) = ll;
        }
        if (n1 < 49) {
            size_t o1 = (size_t)(tokb + n1) * 128 + h * 32 + d;
            __nv_bfloat16 h0, l0, h1, l1;
            split_bf(oacc[nd][2] * inv1, h0, l0);
            split_bf(oacc[nd][3] * inv1, h1, l1);
            __nv_bfloat162 hh; hh.x = h0; hh.y = h1;
            __nv_bfloat162 ll; ll.x = l0; ll.y = l1;
            *(__nv_bfloat162*)(Obf + o1) = hh;
            *(__nv_bfloat162*)(Obf + OMK + o1) = ll;
        }
    }
}

// ------------------------- permutations ------------------------------------
__global__ void __launch_bounds__(256)
winpart_tile(const float* __restrict__ x, __nv_bfloat16* __restrict__ Xbf) {
    __shared__ float tile[32][65];
    const long long XMK = (long long)MTOK * 128;
    int sp0 = blockIdx.x * 64;
    int c0 = blockIdx.y * 32;
    int tid = threadIdx.x;
    {
        int ci = tid >> 3, si = (tid & 7) * 8;
        const float* p = x + (size_t)(c0 + ci) * MTOK + sp0 + si;
        float4 u0 = *(const float4*)p;
        float4 u1 = *(const float4*)(p + 4);
        tile[ci][si + 0] = u0.x; tile[ci][si + 1] = u0.y;
        tile[ci][si + 2] = u0.z; tile[ci][si + 3] = u0.w;
        tile[ci][si + 4] = u1.x; tile[ci][si + 5] = u1.y;
        tile[ci][si + 6] = u1.z; tile[ci][si + 7] = u1.w;
    }
    __syncthreads();
    {
        int si = tid >> 2, cj = (tid & 3) * 8;
        int sp = sp0 + si;
        int hh = sp / HWDIM, ww = sp % HWDIM;
        int out_t = ((hh / 7) * 32 + (ww / 7)) * 49 + (hh % 7) * 7 + (ww % 7);
        size_t ob = (size_t)out_t * 128 + c0 + cj;
#pragma unroll
        for (int k2 = 0; k2 < 4; k2++) {
            float v0 = tile[cj + 2 * k2][si];
            float v1 = tile[cj + 2 * k2 + 1][si];
            __nv_bfloat16 h0, l0, h1, l1;
            split_bf(v0, h0, l0);
            split_bf(v1, h1, l1);
            __nv_bfloat162 hh2; hh2.x = h0; hh2.y = h1;
            __nv_bfloat162 ll2; ll2.x = l0; ll2.y = l1;
            *(__nv_bfloat162*)(Xbf + ob + 2 * k2) = hh2;
            *(__nv_bfloat162*)(Xbf + XMK + ob + 2 * k2) = ll2;
        }
    }
}

__global__ void __launch_bounds__(256)
permute_b2g_tile(const __nv_bfloat16* __restrict__ A, __nv_bfloat16* __restrict__ Xbf) {
    __shared__ float tile[32][129];
    const long long XMK = (long long)MTOK * 128;
    int ho = blockIdx.x;
    int tok1 = blockIdx.y;
    int hi2 = tok1 / 7, wi2 = tok1 % 7;
    int tid = threadIdx.x;
    for (int i = tid; i < 1024; i += 256) {
        int wo = i >> 5, c4 = (i & 31) * 4;
        size_t off = ((size_t)((ho * 32 + wo) * 49 + tok1)) * 128 + c4;
        uint2 uh = *(const uint2*)(A + off);
        uint2 ul = *(const uint2*)(A + XMK + off);
        const unsigned short* hs = (const unsigned short*)&uh;
        const unsigned short* ls = (const unsigned short*)&ul;
#pragma unroll
        for (int k = 0; k < 4; k++) {
            tile[wo][c4 + k] = __bfloat162float(__ushort_as_bfloat16(hs[k])) +
                               __bfloat162float(__ushort_as_bfloat16(ls[k]));
        }
    }
    __syncthreads();
    for (int i = tid; i < 1024; i += 256) {
        int c = i & 127, w4 = (i >> 7) * 4;
        int f = (((c * 32 + ho) * 7 + hi2) * 7 + wi2) * 32;
        int cg = f & 127, s = f >> 7;
        int h2 = s / 224, w2 = s % 224;
        int dtok = ((h2 >> 5) * 7 + (w2 >> 5)) * 1024 + (h2 & 31) * 32 + (w2 & 31);
        size_t d0 = (size_t)dtok * 128 + cg + w4;
        float v0 = tile[w4 + 0][c], v1 = tile[w4 + 1][c];
        float v2 = tile[w4 + 2][c], v3 = tile[w4 + 3][c];
        uint2 ph, pl2;
        ph.x = pack_hi(v0, v1); ph.y = pack_hi(v2, v3);
        pl2.x = pack_lo(v0, v1); pl2.y = pack_lo(v2, v3);
        *(uint2*)(Xbf + d0) = ph;
        *(uint2*)(Xbf + XMK + d0) = pl2;
    }
}

__global__ void permute_g2out_kernel(const float* __restrict__ A, float* __restrict__ out) {
    int idx = (blockIdx.x * 256 + threadIdx.x) * 4;
    if (idx >= MTOK * CCH) return;
    float4 r;
    float* rp = (float*)&r;
#pragma unroll
    for (int k = 0; k < 4; k++) {
        int id = idx + k;
        int w2 = id % HWDIM;
        int t = id / HWDIM;
        int h2 = t % HWDIM;
        int c2 = t / HWDIM;
        int f = (h2 * HWDIM + w2) * CCH + c2;
        int gwo = f % 7;  f /= 7;
        int gwi = f & 31; f >>= 5;
        int ghi = f & 31; f >>= 5;
        int gho = f % 7;  f /= 7;
        int c = f;
        rp[k] = A[((size_t)((gho * 7 + gwo) * 1024 + ghi * 32 + gwi)) * 128 + c];
    }
    *(float4*)(out + idx) = r;
}

// ------------------------- weight pre-split ---------------------------------
struct WParams {
    const float* src[8];
    __nv_bfloat16* dst[8];
    int N[8];
    int K[8];
};
__global__ void convw8(WParams p) {
    int w = blockIdx.y;
    int N = p.N[w], K = p.K[w];
    int NK = N * K;
    const float* src = p.src[w];
    __nv_bfloat16* dst = p.dst[w];
    for (int idx = blockIdx.x * 256 + threadIdx.x; idx < NK; idx += gridDim.x * 256) {
        int n = idx / K, k = idx % K;
        float v = src[idx];
        __nv_bfloat16 h, l;
        split_bf(v, h, l);
        dst[(size_t)k * N + n] = h;
        dst[(size_t)NK + (size_t)k * N + n] = l;
    }
}

// ------------------------- host orchestration -------------------------------
extern "C" void kernel_launch(void* const* d_in, const int* in_sizes, int n_in,
                              void* d_out, int out_size) {
    const float* x = (const float*)d_in[0];
    const float* bp[10];
    const float* gp[10];
    for (int i = 0; i < 10; i++) bp[i] = (const float*)d_in[1 + i];
    for (int i = 0; i < 10; i++) gp[i] = (const float*)d_in[11 + i];

    cudaFuncSetAttribute(gemm_bf, cudaFuncAttributeMaxDynamicSharedMemorySize, GSMEM);
    cudaFuncSetAttribute(flash2, cudaFuncAttributeMaxDynamicSharedMemorySize, FSMEM);
    cudaFuncSetAttribute(fused_mlp, cudaFuncAttributeMaxDynamicSharedMemorySize, FMSMEM);

    float* Out;
    __nv_bfloat16 *Xbf, *QKVbf, *Obf, *Ynbf, *Wbf;
    cudaGetSymbolAddress((void**)&Out, g_Out);
    cudaGetSymbolAddress((void**)&Xbf, g_Xbf);
    cudaGetSymbolAddress((void**)&QKVbf, g_QKVbf);
    cudaGetSymbolAddress((void**)&Obf, g_Obf);
    cudaGetSymbolAddress((void**)&Ynbf, g_Ynbf);
    cudaGetSymbolAddress((void**)&Wbf, g_Wbf);

    const long long XMK = (long long)MTOK * 128;
    const long long QMK = (long long)MTOK * 384;

    WParams wp;
    wp.src[0] = bp[1]; wp.dst[0] = Wbf + 0;      wp.N[0] = 384; wp.K[0] = 128;
    wp.src[1] = bp[2]; wp.dst[1] = Wbf + 98304;  wp.N[1] = 128; wp.K[1] = 128;
    wp.src[2] = bp[6]; wp.dst[2] = Wbf + 131072; wp.N[2] = 512; wp.K[2] = 128;
    wp.src[3] = bp[8]; wp.dst[3] = Wbf + 262144; wp.N[3] = 128; wp.K[3] = 512;
    wp.src[4] = gp[1]; wp.dst[4] = Wbf + 393216; wp.N[4] = 384; wp.K[4] = 128;
    wp.src[5] = gp[2]; wp.dst[5] = Wbf + 491520; wp.N[5] = 128; wp.K[5] = 128;
    wp.src[6] = gp[6]; wp.dst[6] = Wbf + 524288; wp.N[6] = 512; wp.K[6] = 128;
    wp.src[7] = gp[8]; wp.dst[7] = Wbf + 655360; wp.N[7] = 128; wp.K[7] = 512;
    convw8<<<dim3(64, 8), 256>>>(wp);

    // ================= Stage 1: 7x7 windows ==================
    winpart_tile<<<dim3(MTOK / 64, 4), 256>>>(x, Xbf);
    gemm_bf<<<dim3(3, 392), 256, GSMEM>>>(Xbf, XMK, Wbf + 0, 49152, 128, 384,
                                          nullptr, nullptr, 0, nullptr, QKVbf, QMK, 1, nullptr, nullptr);
    attn_small_tc<<<4096, 128>>>(QKVbf, bp[0], Obf);
    gemm_bf<<<dim3(1, 392), 256, GSMEM>>>(Obf, XMK, Wbf + 98304, 16384, 128, 128,
                                          bp[3], Xbf, XMK, nullptr, Ynbf, XMK, 2, bp[4], bp[5]);
    fused_mlp<<<392, 256, FMSMEM>>>(Ynbf, XMK, Wbf + 131072, bp[7], Wbf + 262144, bp[9],
                                    Ynbf, XMK, nullptr, Obf, XMK, 3);

    permute_b2g_tile<<<dim3(32, 49), 256>>>(Obf, Xbf);

    // ================= Stage 2: 32x32 grid ===================
    gemm_bf<<<dim3(3, 392), 256, GSMEM>>>(Xbf, XMK, Wbf + 393216, 49152, 128, 384,
                                          nullptr, nullptr, 0, nullptr, QKVbf, QMK, 1, nullptr, nullptr);
    flash2<<<dim3(8, 196), 256, FSMEM>>>(QKVbf, gp[0], Obf);
    gemm_bf<<<dim3(1, 392), 256, GSMEM>>>(Obf, XMK, Wbf + 491520, 16384, 128, 128,
                                          gp[3], Xbf, XMK, nullptr, Ynbf, XMK, 2, gp[4], gp[5]);
    fused_mlp<<<392, 256, FMSMEM>>>(Ynbf, XMK, Wbf + 524288, gp[7], Wbf + 655360, gp[9],
                                    Ynbf, XMK, Out, nullptr, 0, 0);

    permute_g2out_kernel<<<MTOK * CCH / 1024, 256>>>(Out, (float*)d_out);
}